// round 2
// baseline (speedup 1.0000x reference)
#include <cuda_runtime.h>
#include <cuda_bf16.h>

// ---------------------------------------------------------------------------
// MultiHeadSelfAttention: B=2, N=2048, C=1024, H=16, D=64, fp32.
//   qkv = x @ w_qkv + b_qkv            [4096, 3072]
//   flash attention per (b,h)          [B,H,2048,64]
//   out = attn @ w_out + b_out         [4096, 1024]
// All GEMM inner loops use packed fma.rn.f32x2 (full-rate fp32 on sm_103a;
// 3-reg FFMA is half rate).
// ---------------------------------------------------------------------------

#define NB    2
#define NSEQ  2048
#define NC    1024
#define NH    16
#define ND    64
#define NTOK  (NB * NSEQ)       // 4096
#define C3    (3 * NC)          // 3072

// Scratch (static __device__ arrays: allocation-guard safe)
__device__ float g_qkv[NTOK * C3];     // 48 MiB
__device__ float g_attn[NTOK * NC];    // 16 MiB

// ---------------- f32x2 helpers ----------------
__device__ __forceinline__ unsigned long long pack2(float x, float y) {
    unsigned long long r;
    asm("mov.b64 %0, {%1, %2};" : "=l"(r) : "f"(x), "f"(y));
    return r;
}
__device__ __forceinline__ void fma2(unsigned long long& d,
                                     unsigned long long a,
                                     unsigned long long b) {
    asm("fma.rn.f32x2 %0, %1, %2, %0;" : "+l"(d) : "l"(a), "l"(b));
}
__device__ __forceinline__ unsigned long long mul2(unsigned long long a,
                                                   unsigned long long b) {
    unsigned long long r;
    asm("mul.rn.f32x2 %0, %1, %2;" : "=l"(r) : "l"(a), "l"(b));
    return r;
}
__device__ __forceinline__ float2 unpack2(unsigned long long v) {
    float2 r;
    asm("mov.b64 {%0, %1}, %2;" : "=f"(r.x), "=f"(r.y) : "l"(v));
    return r;
}

// ---------------------------------------------------------------------------
// SGEMM: C[M,N] = A[M,K] @ B[K,N] + bias[N]
// BM=BN=128, BK=16, 256 threads, 8x8 microtile with f32x2 (j-paired).
// Requires M%128==0, N%128==0, K%16==0 (true for all uses here).
// ---------------------------------------------------------------------------
#define BM 128
#define BN 128
#define BK 16

__global__ __launch_bounds__(256) void sgemm_bias_kernel(
    const float* __restrict__ A, const float* __restrict__ B,
    const float* __restrict__ bias, float* __restrict__ C,
    int M, int N, int K)
{
    __shared__ float As[BM * BK];
    __shared__ float Bs[BK * BN];

    const int t  = threadIdx.x;
    const int tx = t & 15;        // 0..15  -> 8 cols
    const int ty = t >> 4;        // 0..15  -> 8 rows
    const int bm = blockIdx.y * BM;
    const int bn = blockIdx.x * BN;

    // load mapping
    const int ar = t >> 2;            // 0..63
    const int ak = (t & 3) << 2;      // 0,4,8,12
    const int br = t >> 5;            // 0..7
    const int bc = (t & 31) << 2;     // 0..124

    const float* Aptr = A + (size_t)(bm + ar) * K + ak;
    const float* Bptr = B + (size_t)br * N + bn + bc;

    unsigned long long acc[8][4];
#pragma unroll
    for (int i = 0; i < 8; i++)
#pragma unroll
        for (int j = 0; j < 4; j++) acc[i][j] = 0ull;

    float4 ra0 = *(const float4*)(Aptr);
    float4 ra1 = *(const float4*)(Aptr + (size_t)64 * K);
    float4 rb0 = *(const float4*)(Bptr);
    float4 rb1 = *(const float4*)(Bptr + (size_t)8 * N);

    const int NK = K / BK;
    for (int kt = 0; kt < NK; kt++) {
        *(float4*)&As[ar * BK + ak]        = ra0;
        *(float4*)&As[(ar + 64) * BK + ak] = ra1;
        *(float4*)&Bs[br * BN + bc]        = rb0;
        *(float4*)&Bs[(br + 8) * BN + bc]  = rb1;
        __syncthreads();

        if (kt + 1 < NK) {
            ra0 = *(const float4*)(Aptr + (kt + 1) * BK);
            ra1 = *(const float4*)(Aptr + (size_t)64 * K + (kt + 1) * BK);
            rb0 = *(const float4*)(Bptr + (size_t)(kt + 1) * BK * N);
            rb1 = *(const float4*)(Bptr + (size_t)(8 + (kt + 1) * BK) * N);
        }

#pragma unroll
        for (int k = 0; k < BK; k++) {
            unsigned long long b2[4];
#pragma unroll
            for (int j = 0; j < 4; j++)
                b2[j] = *(const unsigned long long*)&Bs[k * BN + tx * 8 + 2 * j];
#pragma unroll
            for (int i = 0; i < 8; i++) {
                float a = As[(ty * 8 + i) * BK + k];
                unsigned long long a2 = pack2(a, a);
#pragma unroll
                for (int j = 0; j < 4; j++) fma2(acc[i][j], a2, b2[j]);
            }
        }
        __syncthreads();
    }

#pragma unroll
    for (int i = 0; i < 8; i++) {
        const size_t row = bm + ty * 8 + i;
#pragma unroll
        for (int j = 0; j < 4; j++) {
            float2 v = unpack2(acc[i][j]);
            const int col = bn + tx * 8 + 2 * j;
            v.x += bias[col];
            v.y += bias[col + 1];
            *(float2*)&C[row * N + col] = v;
        }
    }
}

// ---------------------------------------------------------------------------
// Flash attention fp32: one block per (b,h, 64-row Q tile).
// Br=Bc=64, 256 threads, 4x4 microtiles (f32x2, j-paired).
// ---------------------------------------------------------------------------
#define SQ 65   // Qs row stride
#define SK 65   // K tile row stride
#define SV 66   // V tile row stride (even -> direct 8B loads)
#define SS 65   // S tile row stride

__global__ __launch_bounds__(256) void attn_kernel(
    const float* __restrict__ qkv, float* __restrict__ outp)
{
    extern __shared__ float sm[];
    float* Qs   = sm;                    // 64*SQ
    float* KV   = Qs + 64 * SQ;          // 64*SV (K then V)
    float* Ss   = KV + 64 * SV;          // 64*SS
    float* m_sh = Ss + 64 * SS;          // 64
    float* l_sh = m_sh + 64;             // 64
    float* a_sh = l_sh + 64;             // 64

    const int t  = threadIdx.x;
    const int tx = t & 15;     // cols 4*tx..4*tx+3
    const int ty = t >> 4;     // rows 4*ty..4*ty+3
    const int bh = blockIdx.x;              // 0..31
    const int b  = bh >> 4, h = bh & 15;
    const int n0 = blockIdx.y * 64;

    const int lr = t >> 2;            // 0..63  (tile row for loads)
    const int lc = (t & 3) << 4;      // 0,16,32,48

    const float* qbase = qkv + (size_t)(b * NSEQ + n0) * C3 + h * ND;
    const float* kbase = qkv + (size_t)(b * NSEQ) * C3 + NC + h * ND;
    const float* vbase = kbase + NC;

    // load Q tile
#pragma unroll
    for (int p = 0; p < 4; p++) {
        float4 v = *(const float4*)(qbase + (size_t)lr * C3 + lc + p * 4);
        Qs[lr * SQ + lc + p * 4 + 0] = v.x;
        Qs[lr * SQ + lc + p * 4 + 1] = v.y;
        Qs[lr * SQ + lc + p * 4 + 2] = v.z;
        Qs[lr * SQ + lc + p * 4 + 3] = v.w;
    }
    if (t < 64) { m_sh[t] = -1e30f; l_sh[t] = 0.0f; }

    unsigned long long accO[4][2];
#pragma unroll
    for (int i = 0; i < 4; i++) { accO[i][0] = 0ull; accO[i][1] = 0ull; }

    __syncthreads();

    for (int kt0 = 0; kt0 < NSEQ; kt0 += 64) {
        // ---- load K tile ----
#pragma unroll
        for (int p = 0; p < 4; p++) {
            float4 v = *(const float4*)(kbase + (size_t)(kt0 + lr) * C3 + lc + p * 4);
            KV[lr * SK + lc + p * 4 + 0] = v.x;
            KV[lr * SK + lc + p * 4 + 1] = v.y;
            KV[lr * SK + lc + p * 4 + 2] = v.z;
            KV[lr * SK + lc + p * 4 + 3] = v.w;
        }
        __syncthreads();

        // ---- S = Q @ K^T (reduce over d) ----
        unsigned long long accS[4][2];
#pragma unroll
        for (int i = 0; i < 4; i++) { accS[i][0] = 0ull; accS[i][1] = 0ull; }

#pragma unroll 8
        for (int d = 0; d < 64; d++) {
            float k0 = KV[(tx * 4 + 0) * SK + d];
            float k1 = KV[(tx * 4 + 1) * SK + d];
            float k2 = KV[(tx * 4 + 2) * SK + d];
            float k3 = KV[(tx * 4 + 3) * SK + d];
            unsigned long long b0 = pack2(k0, k1);
            unsigned long long b1 = pack2(k2, k3);
#pragma unroll
            for (int i = 0; i < 4; i++) {
                float a = Qs[(ty * 4 + i) * SQ + d];
                unsigned long long a2 = pack2(a, a);
                fma2(accS[i][0], a2, b0);
                fma2(accS[i][1], a2, b1);
            }
        }
        // store S tile
#pragma unroll
        for (int i = 0; i < 4; i++) {
#pragma unroll
            for (int j = 0; j < 2; j++) {
                float2 v = unpack2(accS[i][j]);
                Ss[(ty * 4 + i) * SS + tx * 4 + 2 * j + 0] = v.x;
                Ss[(ty * 4 + i) * SS + tx * 4 + 2 * j + 1] = v.y;
            }
        }
        __syncthreads();   // S-gemm done reading KV; S fully stored

        // ---- load V tile (overwrites KV) ----
#pragma unroll
        for (int p = 0; p < 4; p++) {
            float4 v = *(const float4*)(vbase + (size_t)(kt0 + lr) * C3 + lc + p * 4);
            KV[lr * SV + lc + p * 4 + 0] = v.x;
            KV[lr * SV + lc + p * 4 + 1] = v.y;
            KV[lr * SV + lc + p * 4 + 2] = v.z;
            KV[lr * SV + lc + p * 4 + 3] = v.w;
        }

        // ---- online softmax (rows, t<64) ----
        if (t < 64) {
            const float scale = 0.125f;  // 1/sqrt(64)
            float mold = m_sh[t];
            float mx = mold;
            for (int c = 0; c < 64; c++)
                mx = fmaxf(mx, Ss[t * SS + c] * scale);
            float al = __expf(mold - mx);
            float ls = 0.0f;
            for (int c = 0; c < 64; c++) {
                float p = __expf(Ss[t * SS + c] * scale - mx);
                Ss[t * SS + c] = p;
                ls += p;
            }
            l_sh[t] = l_sh[t] * al + ls;
            m_sh[t] = mx;
            a_sh[t] = al;
        }
        __syncthreads();   // V loaded, P + alpha ready

        // ---- rescale O, then O += P @ V (reduce over c) ----
#pragma unroll
        for (int i = 0; i < 4; i++) {
            float al = a_sh[ty * 4 + i];
            unsigned long long al2 = pack2(al, al);
            accO[i][0] = mul2(accO[i][0], al2);
            accO[i][1] = mul2(accO[i][1], al2);
        }
#pragma unroll 8
        for (int c = 0; c < 64; c++) {
            unsigned long long b0 = *(const unsigned long long*)&KV[c * SV + tx * 4];
            unsigned long long b1 = *(const unsigned long long*)&KV[c * SV + tx * 4 + 2];
#pragma unroll
            for (int i = 0; i < 4; i++) {
                float a = Ss[(ty * 4 + i) * SS + c];
                unsigned long long a2 = pack2(a, a);
                fma2(accO[i][0], a2, b0);
                fma2(accO[i][1], a2, b1);
            }
        }
        __syncthreads();   // PV done before next tile overwrites KV/Ss
    }

    // ---- epilogue: O /= l, write [B,N,H,D] ----
#pragma unroll
    for (int i = 0; i < 4; i++) {
        const float linv = 1.0f / l_sh[ty * 4 + i];
        const size_t row = (size_t)(b * NSEQ + n0 + ty * 4 + i) * NC + h * ND;
#pragma unroll
        for (int j = 0; j < 2; j++) {
            float2 v = unpack2(accO[i][j]);
            v.x *= linv;
            v.y *= linv;
            *(float2*)&outp[row + tx * 4 + 2 * j] = v;
        }
    }
}

// ---------------------------------------------------------------------------
extern "C" void kernel_launch(void* const* d_in, const int* in_sizes, int n_in,
                              void* d_out, int out_size)
{
    const float* x     = (const float*)d_in[0];
    const float* w_qkv = (const float*)d_in[1];
    const float* b_qkv = (const float*)d_in[2];
    const float* w_out = (const float*)d_in[3];
    const float* b_out = (const float*)d_in[4];
    float* out = (float*)d_out;

    float* qkvbuf  = nullptr;
    float* attnbuf = nullptr;
    cudaGetSymbolAddress((void**)&qkvbuf, g_qkv);
    cudaGetSymbolAddress((void**)&attnbuf, g_attn);

    // attention dynamic smem: Qs + KV + Ss + (m,l,alpha)
    const int smem_attn = (64 * SQ + 64 * SV + 64 * SS + 3 * 64) * (int)sizeof(float);
    cudaFuncSetAttribute(attn_kernel,
                         cudaFuncAttributeMaxDynamicSharedMemorySize, smem_attn);

    // 1) qkv = x @ w_qkv + b_qkv
    {
        dim3 grid(C3 / BN, NTOK / BM);   // (24, 32)
        sgemm_bias_kernel<<<grid, 256>>>(x, w_qkv, b_qkv, qkvbuf, NTOK, C3, NC);
    }
    // 2) flash attention
    {
        dim3 grid(NB * NH, NSEQ / 64);   // (32, 32)
        attn_kernel<<<grid, 256, smem_attn>>>(qkvbuf, attnbuf);
    }
    // 3) out = attn @ w_out + b_out
    {
        dim3 grid(NC / BN, NTOK / BM);   // (8, 32)
        sgemm_bias_kernel<<<grid, 256>>>(attnbuf, w_out, b_out, out, NTOK, NC, NC);
    }
}

// round 9
// speedup vs baseline: 2.2782x; 2.2782x over previous
#include <cuda_runtime.h>
#include <cuda_bf16.h>
#include <cstdint>

// ---------------------------------------------------------------------------
// MultiHeadSelfAttention: B=2, N=2048, C=1024, H=16, D=64, fp32 in/out.
//   qkv = x @ w_qkv + b_qkv     [4096,3072]   <- mma.sync tf32 (HMMA)
//   flash attention (fp32 SIMT) [B,H,2048,64]
//   out = attn @ w_out + b_out  [4096,1024]   <- mma.sync tf32 (HMMA)
// tcgen05 is unavailable (harness compiles via compute_103 PTX target), so
// the tensor pipe is driven with sm_80-class mma.sync which ptxas accepts.
// ---------------------------------------------------------------------------

#define NB    2
#define NSEQ  2048
#define NC    1024
#define NH    16
#define ND    64
#define NTOK  (NB * NSEQ)       // 4096
#define C3    (3 * NC)          // 3072

// Scratch (static __device__ arrays: allocation-guard safe)
__device__ float g_qkv[NTOK * C3];      // 48 MiB
__device__ float g_attn[NTOK * NC];     // 16 MiB

// ---------------- helpers ----------------
__device__ __forceinline__ uint32_t f2tf32(float f) {
    uint32_t r;
    asm("cvt.rna.tf32.f32 %0, %1;" : "=r"(r) : "f"(f));
    return r;
}

#define MMA_TF32(cc, aa, b0v, b1v)                                            \
    asm volatile("mma.sync.aligned.m16n8k8.row.col.f32.tf32.tf32.f32 "        \
                 "{%0,%1,%2,%3}, {%4,%5,%6,%7}, {%8,%9}, {%0,%1,%2,%3};"      \
                 : "+f"((cc)[0]), "+f"((cc)[1]), "+f"((cc)[2]), "+f"((cc)[3]) \
                 : "r"((aa)[0]), "r"((aa)[1]), "r"((aa)[2]), "r"((aa)[3]),    \
                   "r"(b0v), "r"(b1v))

// f32x2 helpers (attention)
__device__ __forceinline__ unsigned long long pack2(float x, float y) {
    unsigned long long r;
    asm("mov.b64 %0, {%1, %2};" : "=l"(r) : "f"(x), "f"(y));
    return r;
}
__device__ __forceinline__ void fma2(unsigned long long& d,
                                     unsigned long long a,
                                     unsigned long long b) {
    asm("fma.rn.f32x2 %0, %1, %2, %0;" : "+l"(d) : "l"(a), "l"(b));
}
__device__ __forceinline__ unsigned long long mul2(unsigned long long a,
                                                   unsigned long long b) {
    unsigned long long r;
    asm("mul.rn.f32x2 %0, %1, %2;" : "=l"(r) : "l"(a), "l"(b));
    return r;
}
__device__ __forceinline__ float2 unpack2(unsigned long long v) {
    float2 r;
    asm("mov.b64 {%0, %1}, %2;" : "=f"(r.x), "=f"(r.y) : "l"(v));
    return r;
}

// ===========================================================================
// GEMM via mma.sync tf32:  C[M,N] = A[M,K] @ B[K,N] + bias[N]
// Block tile 128x128, BK=32, 256 threads (8 warps, warp tile 32x64).
// SMEM (dynamic, 64KB): double-buffered A (tf32, XOR-swizzled) + B.
//   As addr (floats): m*32 + (k ^ ((m&7)<<2))   -> frag loads conflict-free
//   Bs addr (floats): k*128 + (n ^ ((k&3)<<3))  -> frag loads conflict-free
// ===========================================================================
#define GBM 128
#define GBN 128
#define GBK 32
#define GEMM_SMEM (4 * 4096 * 4)   // 2 stages * (A 4096 + B 4096) floats

__global__ __launch_bounds__(256) void gemm_mma_kernel(
    const float* __restrict__ A, const float* __restrict__ B,
    const float* __restrict__ bias, float* __restrict__ C,
    int M, int N, int K)
{
    extern __shared__ uint32_t smu[];
    uint32_t* As = smu;             // [2][128*32]
    uint32_t* Bs = smu + 2 * 4096;  // [2][32*128]

    const int t    = threadIdx.x;
    const int lane = t & 31;
    const int lr   = lane >> 2;       // 0..7
    const int lc   = lane & 3;        // 0..3
    const int wm   = ((t >> 5) & 3) * 32;   // warp m offset
    const int wn   = (t >> 7) * 64;         // warp n offset
    const int bm   = blockIdx.y * GBM;
    const int bn   = blockIdx.x * GBN;
    const int NK   = K / GBK;

    float c[2][8][4];
#pragma unroll
    for (int u = 0; u < 2; u++)
#pragma unroll
        for (int j = 0; j < 8; j++)
#pragma unroll
            for (int q = 0; q < 4; q++) c[u][j][q] = 0.0f;

    // ---- stage chunk 0 ----
#pragma unroll
    for (int i = 0; i < 4; i++) {
        const int idx = t + 256 * i;
        const int m = idx >> 3, k = (idx & 7) << 2;
        float4 v = *(const float4*)(A + (size_t)(bm + m) * K + k);
        uint4 w = { f2tf32(v.x), f2tf32(v.y), f2tf32(v.z), f2tf32(v.w) };
        *(uint4*)(As + m * 32 + (k ^ ((m & 7) << 2))) = w;
    }
#pragma unroll
    for (int i = 0; i < 4; i++) {
        const int idx = t + 256 * i;
        const int kk = idx >> 5, n = (idx & 31) << 2;
        float4 v = *(const float4*)(B + (size_t)kk * N + bn + n);
        uint4 w = { f2tf32(v.x), f2tf32(v.y), f2tf32(v.z), f2tf32(v.w) };
        *(uint4*)(Bs + kk * 128 + (n ^ ((kk & 3) << 3))) = w;
    }
    __syncthreads();

    for (int kt = 0; kt < NK; kt++) {
        const int cur = kt & 1;
        const uint32_t* as = As + cur * 4096;
        const uint32_t* bs = Bs + cur * 4096;

        // prefetch next chunk into regs
        float4 pa[4], pb[4];
        if (kt + 1 < NK) {
            const int kofs = (kt + 1) * GBK;
#pragma unroll
            for (int i = 0; i < 4; i++) {
                const int idx = t + 256 * i;
                const int m = idx >> 3, k = (idx & 7) << 2;
                pa[i] = *(const float4*)(A + (size_t)(bm + m) * K + kofs + k);
            }
#pragma unroll
            for (int i = 0; i < 4; i++) {
                const int idx = t + 256 * i;
                const int kk = idx >> 5, n = (idx & 31) << 2;
                pb[i] = *(const float4*)(B + (size_t)(kofs + kk) * N + bn + n);
            }
        }

        // ---- compute on current buffers ----
#pragma unroll
        for (int s = 0; s < 4; s++) {
            const int kk = s * 8;
            uint32_t a[2][4];
#pragma unroll
            for (int u = 0; u < 2; u++) {
                const int m0 = wm + u * 16 + lr;
                const int sw = (m0 & 7) << 2;
                a[u][0] = as[m0 * 32 + ((kk + lc) ^ sw)];
                a[u][1] = as[(m0 + 8) * 32 + ((kk + lc) ^ sw)];
                a[u][2] = as[m0 * 32 + ((kk + lc + 4) ^ sw)];
                a[u][3] = as[(m0 + 8) * 32 + ((kk + lc + 4) ^ sw)];
            }
#pragma unroll
            for (int j = 0; j < 8; j++) {
                const int n0 = wn + j * 8 + lr;
                const int kb = kk + lc;
                const int sw = (kb & 3) << 3;
                const uint32_t b0 = bs[kb * 128 + (n0 ^ sw)];
                const uint32_t b1 = bs[(kb + 4) * 128 + (n0 ^ sw)];
                MMA_TF32(c[0][j], a[0], b0, b1);
                MMA_TF32(c[1][j], a[1], b0, b1);
            }
        }

        // ---- store prefetched chunk into other buffers ----
        if (kt + 1 < NK) {
            uint32_t* an = As + (cur ^ 1) * 4096;
            uint32_t* bnx = Bs + (cur ^ 1) * 4096;
#pragma unroll
            for (int i = 0; i < 4; i++) {
                const int idx = t + 256 * i;
                const int m = idx >> 3, k = (idx & 7) << 2;
                uint4 w = { f2tf32(pa[i].x), f2tf32(pa[i].y),
                            f2tf32(pa[i].z), f2tf32(pa[i].w) };
                *(uint4*)(an + m * 32 + (k ^ ((m & 7) << 2))) = w;
            }
#pragma unroll
            for (int i = 0; i < 4; i++) {
                const int idx = t + 256 * i;
                const int kk = idx >> 5, n = (idx & 31) << 2;
                uint4 w = { f2tf32(pb[i].x), f2tf32(pb[i].y),
                            f2tf32(pb[i].z), f2tf32(pb[i].w) };
                *(uint4*)(bnx + kk * 128 + (n ^ ((kk & 3) << 3))) = w;
            }
        }
        __syncthreads();
    }

    // ---- epilogue: C frags + bias -> global ----
#pragma unroll
    for (int u = 0; u < 2; u++) {
        const int row = bm + wm + u * 16 + lr;
#pragma unroll
        for (int j = 0; j < 8; j++) {
            const int col = bn + wn + j * 8 + 2 * lc;
            const float bx = __ldg(&bias[col]);
            const float by = __ldg(&bias[col + 1]);
            float2 v0 = { c[u][j][0] + bx, c[u][j][1] + by };
            float2 v1 = { c[u][j][2] + bx, c[u][j][3] + by };
            *(float2*)(C + (size_t)row * N + col)       = v0;
            *(float2*)(C + (size_t)(row + 8) * N + col) = v1;
        }
    }
}

// ===========================================================================
// Flash attention fp32: one block per (b,h, 64-row Q tile). 256 threads.
// Softmax parallelized 4 threads/row with butterfly shuffles.
// ===========================================================================
#define SQ 65
#define SK 65
#define SV 66
#define SS 65

__global__ __launch_bounds__(256) void attn_kernel(
    const float* __restrict__ qkv, float* __restrict__ outp)
{
    extern __shared__ float smf[];
    float* Qs   = smf;
    float* KV   = Qs + 64 * SQ;
    float* Ss   = KV + 64 * SV;
    float* m_sh = Ss + 64 * SS;
    float* l_sh = m_sh + 64;
    float* a_sh = l_sh + 64;

    const int t  = threadIdx.x;
    const int tx = t & 15;
    const int ty = t >> 4;
    const int bh = blockIdx.x;
    const int b  = bh >> 4, h = bh & 15;
    const int n0 = blockIdx.y * 64;

    const int lr = t >> 2;
    const int lc = (t & 3) << 4;

    const float* qbase = qkv + (size_t)(b * NSEQ + n0) * C3 + h * ND;
    const float* kbase = qkv + (size_t)(b * NSEQ) * C3 + NC + h * ND;
    const float* vbase = kbase + NC;

#pragma unroll
    for (int p = 0; p < 4; p++) {
        float4 v = *(const float4*)(qbase + (size_t)lr * C3 + lc + p * 4);
        Qs[lr * SQ + lc + p * 4 + 0] = v.x;
        Qs[lr * SQ + lc + p * 4 + 1] = v.y;
        Qs[lr * SQ + lc + p * 4 + 2] = v.z;
        Qs[lr * SQ + lc + p * 4 + 3] = v.w;
    }
    if (t < 64) { m_sh[t] = -1e30f; l_sh[t] = 0.0f; }

    unsigned long long accO[4][2];
#pragma unroll
    for (int i = 0; i < 4; i++) { accO[i][0] = 0ull; accO[i][1] = 0ull; }

    __syncthreads();

    for (int kt0 = 0; kt0 < NSEQ; kt0 += 64) {
#pragma unroll
        for (int p = 0; p < 4; p++) {
            float4 v = *(const float4*)(kbase + (size_t)(kt0 + lr) * C3 + lc + p * 4);
            KV[lr * SK + lc + p * 4 + 0] = v.x;
            KV[lr * SK + lc + p * 4 + 1] = v.y;
            KV[lr * SK + lc + p * 4 + 2] = v.z;
            KV[lr * SK + lc + p * 4 + 3] = v.w;
        }
        __syncthreads();

        unsigned long long accS[4][2];
#pragma unroll
        for (int i = 0; i < 4; i++) { accS[i][0] = 0ull; accS[i][1] = 0ull; }

#pragma unroll 8
        for (int d = 0; d < 64; d++) {
            float k0 = KV[(tx * 4 + 0) * SK + d];
            float k1 = KV[(tx * 4 + 1) * SK + d];
            float k2 = KV[(tx * 4 + 2) * SK + d];
            float k3 = KV[(tx * 4 + 3) * SK + d];
            unsigned long long b0 = pack2(k0, k1);
            unsigned long long b1 = pack2(k2, k3);
#pragma unroll
            for (int i = 0; i < 4; i++) {
                float a = Qs[(ty * 4 + i) * SQ + d];
                unsigned long long a2 = pack2(a, a);
                fma2(accS[i][0], a2, b0);
                fma2(accS[i][1], a2, b1);
            }
        }
#pragma unroll
        for (int i = 0; i < 4; i++) {
#pragma unroll
            for (int j = 0; j < 2; j++) {
                float2 v = unpack2(accS[i][j]);
                Ss[(ty * 4 + i) * SS + tx * 4 + 2 * j + 0] = v.x;
                Ss[(ty * 4 + i) * SS + tx * 4 + 2 * j + 1] = v.y;
            }
        }
        __syncthreads();

        // ---- load V tile (overwrites KV) ----
#pragma unroll
        for (int p = 0; p < 4; p++) {
            float4 v = *(const float4*)(vbase + (size_t)(kt0 + lr) * C3 + lc + p * 4);
            KV[lr * SV + lc + p * 4 + 0] = v.x;
            KV[lr * SV + lc + p * 4 + 1] = v.y;
            KV[lr * SV + lc + p * 4 + 2] = v.z;
            KV[lr * SV + lc + p * 4 + 3] = v.w;
        }

        // ---- online softmax: 4 threads per row, 16 cols each ----
        {
            const float scale = 0.125f;   // 1/sqrt(64)
            const int row = t >> 2, q = t & 3;
            float* srow = Ss + row * SS + q * 16;
            const float mold = m_sh[row];
            float mx = mold;
#pragma unroll
            for (int cc = 0; cc < 16; cc++)
                mx = fmaxf(mx, srow[cc] * scale);
            mx = fmaxf(mx, __shfl_xor_sync(0xffffffffu, mx, 1));
            mx = fmaxf(mx, __shfl_xor_sync(0xffffffffu, mx, 2));
            float ls = 0.0f;
#pragma unroll
            for (int cc = 0; cc < 16; cc++) {
                float p = __expf(srow[cc] * scale - mx);
                srow[cc] = p;
                ls += p;
            }
            ls += __shfl_xor_sync(0xffffffffu, ls, 1);
            ls += __shfl_xor_sync(0xffffffffu, ls, 2);
            if (q == 0) {
                const float al = __expf(mold - mx);
                l_sh[row] = l_sh[row] * al + ls;
                m_sh[row] = mx;
                a_sh[row] = al;
            }
        }
        __syncthreads();

#pragma unroll
        for (int i = 0; i < 4; i++) {
            float al = a_sh[ty * 4 + i];
            unsigned long long al2 = pack2(al, al);
            accO[i][0] = mul2(accO[i][0], al2);
            accO[i][1] = mul2(accO[i][1], al2);
        }
#pragma unroll 8
        for (int cc = 0; cc < 64; cc++) {
            unsigned long long b0 = *(const unsigned long long*)&KV[cc * SV + tx * 4];
            unsigned long long b1 = *(const unsigned long long*)&KV[cc * SV + tx * 4 + 2];
#pragma unroll
            for (int i = 0; i < 4; i++) {
                float a = Ss[(ty * 4 + i) * SS + cc];
                unsigned long long a2 = pack2(a, a);
                fma2(accO[i][0], a2, b0);
                fma2(accO[i][1], a2, b1);
            }
        }
        __syncthreads();
    }

#pragma unroll
    for (int i = 0; i < 4; i++) {
        const float linv = 1.0f / l_sh[ty * 4 + i];
        const size_t row = (size_t)(b * NSEQ + n0 + ty * 4 + i) * NC + h * ND;
#pragma unroll
        for (int j = 0; j < 2; j++) {
            float2 v = unpack2(accO[i][j]);
            v.x *= linv;
            v.y *= linv;
            *(float2*)&outp[row + tx * 4 + 2 * j] = v;
        }
    }
}

// ---------------------------------------------------------------------------
extern "C" void kernel_launch(void* const* d_in, const int* in_sizes, int n_in,
                              void* d_out, int out_size)
{
    const float* x     = (const float*)d_in[0];
    const float* w_qkv = (const float*)d_in[1];
    const float* b_qkv = (const float*)d_in[2];
    const float* w_out = (const float*)d_in[3];
    const float* b_out = (const float*)d_in[4];
    float* out = (float*)d_out;

    float *qkvbuf = nullptr, *attnbuf = nullptr;
    cudaGetSymbolAddress((void**)&qkvbuf, g_qkv);
    cudaGetSymbolAddress((void**)&attnbuf, g_attn);

    const int smem_attn = (64 * SQ + 64 * SV + 64 * SS + 3 * 64) * (int)sizeof(float);
    cudaFuncSetAttribute(attn_kernel,
                         cudaFuncAttributeMaxDynamicSharedMemorySize, smem_attn);
    cudaFuncSetAttribute(gemm_mma_kernel,
                         cudaFuncAttributeMaxDynamicSharedMemorySize, GEMM_SMEM);

    // 1) qkv = x @ w_qkv + b_qkv   (mma.sync tf32)
    {
        dim3 grid(C3 / GBN, NTOK / GBM);   // (24, 32)
        gemm_mma_kernel<<<grid, 256, GEMM_SMEM>>>(x, w_qkv, b_qkv, qkvbuf,
                                                  NTOK, C3, NC);
    }
    // 2) flash attention (fp32)
    {
        dim3 grid(NB * NH, NSEQ / 64);     // (32, 32)
        attn_kernel<<<grid, 256, smem_attn>>>(qkvbuf, attnbuf);
    }
    // 3) out = attn @ w_out + b_out  (mma.sync tf32)
    {
        dim3 grid(NC / GBN, NTOK / GBM);   // (8, 32)
        gemm_mma_kernel<<<grid, 256, GEMM_SMEM>>>(attnbuf, w_out, b_out, out,
                                                  NTOK, NC, NC);
    }
}

// round 12
// speedup vs baseline: 4.6708x; 2.0502x over previous
#include <cuda_runtime.h>
#include <cuda_bf16.h>
#include <cstdint>

// ---------------------------------------------------------------------------
// MultiHeadSelfAttention: B=2, N=2048, C=1024, H=16, D=64, fp32 in/out.
//   qkv = x @ w_qkv + b_qkv     [4096,3072]   <- mma.sync tf32 (HMMA)
//   flash attention             [B,H,2048,64] <- mma.sync tf32 (HMMA)
//   out = attn @ w_out + b_out  [4096,1024]   <- mma.sync tf32 (HMMA)
// ---------------------------------------------------------------------------

#define NB    2
#define NSEQ  2048
#define NC    1024
#define NH    16
#define ND    64
#define NTOK  (NB * NSEQ)       // 4096
#define C3    (3 * NC)          // 3072

__device__ float g_qkv[NTOK * C3];      // 48 MiB
__device__ float g_attn[NTOK * NC];     // 16 MiB

// ---------------- helpers ----------------
__device__ __forceinline__ uint32_t f2tf32(float f) {
    uint32_t r;
    asm("cvt.rna.tf32.f32 %0, %1;" : "=r"(r) : "f"(f));
    return r;
}

#define MMA_TF32(cc, aa, b0v, b1v)                                            \
    asm volatile("mma.sync.aligned.m16n8k8.row.col.f32.tf32.tf32.f32 "        \
                 "{%0,%1,%2,%3}, {%4,%5,%6,%7}, {%8,%9}, {%0,%1,%2,%3};"      \
                 : "+f"((cc)[0]), "+f"((cc)[1]), "+f"((cc)[2]), "+f"((cc)[3]) \
                 : "r"((aa)[0]), "r"((aa)[1]), "r"((aa)[2]), "r"((aa)[3]),    \
                   "r"(b0v), "r"(b1v))

// ===========================================================================
// GEMM via mma.sync tf32 (unchanged from R9 — validated).
// ===========================================================================
#define GBM 128
#define GBN 128
#define GBK 32
#define GEMM_SMEM (4 * 4096 * 4)

__global__ __launch_bounds__(256) void gemm_mma_kernel(
    const float* __restrict__ A, const float* __restrict__ B,
    const float* __restrict__ bias, float* __restrict__ C,
    int M, int N, int K)
{
    extern __shared__ uint32_t smu[];
    uint32_t* As = smu;
    uint32_t* Bs = smu + 2 * 4096;

    const int t    = threadIdx.x;
    const int lane = t & 31;
    const int lr   = lane >> 2;
    const int lc   = lane & 3;
    const int wm   = ((t >> 5) & 3) * 32;
    const int wn   = (t >> 7) * 64;
    const int bm   = blockIdx.y * GBM;
    const int bn   = blockIdx.x * GBN;
    const int NK   = K / GBK;

    float c[2][8][4];
#pragma unroll
    for (int u = 0; u < 2; u++)
#pragma unroll
        for (int j = 0; j < 8; j++)
#pragma unroll
            for (int q = 0; q < 4; q++) c[u][j][q] = 0.0f;

#pragma unroll
    for (int i = 0; i < 4; i++) {
        const int idx = t + 256 * i;
        const int m = idx >> 3, k = (idx & 7) << 2;
        float4 v = *(const float4*)(A + (size_t)(bm + m) * K + k);
        uint4 w = { f2tf32(v.x), f2tf32(v.y), f2tf32(v.z), f2tf32(v.w) };
        *(uint4*)(As + m * 32 + (k ^ ((m & 7) << 2))) = w;
    }
#pragma unroll
    for (int i = 0; i < 4; i++) {
        const int idx = t + 256 * i;
        const int kk = idx >> 5, n = (idx & 31) << 2;
        float4 v = *(const float4*)(B + (size_t)kk * N + bn + n);
        uint4 w = { f2tf32(v.x), f2tf32(v.y), f2tf32(v.z), f2tf32(v.w) };
        *(uint4*)(Bs + kk * 128 + (n ^ ((kk & 3) << 3))) = w;
    }
    __syncthreads();

    for (int kt = 0; kt < NK; kt++) {
        const int cur = kt & 1;
        const uint32_t* as = As + cur * 4096;
        const uint32_t* bs = Bs + cur * 4096;

        float4 pa[4], pb[4];
        if (kt + 1 < NK) {
            const int kofs = (kt + 1) * GBK;
#pragma unroll
            for (int i = 0; i < 4; i++) {
                const int idx = t + 256 * i;
                const int m = idx >> 3, k = (idx & 7) << 2;
                pa[i] = *(const float4*)(A + (size_t)(bm + m) * K + kofs + k);
            }
#pragma unroll
            for (int i = 0; i < 4; i++) {
                const int idx = t + 256 * i;
                const int kk = idx >> 5, n = (idx & 31) << 2;
                pb[i] = *(const float4*)(B + (size_t)(kofs + kk) * N + bn + n);
            }
        }

#pragma unroll
        for (int s = 0; s < 4; s++) {
            const int kk = s * 8;
            uint32_t a[2][4];
#pragma unroll
            for (int u = 0; u < 2; u++) {
                const int m0 = wm + u * 16 + lr;
                const int sw = (m0 & 7) << 2;
                a[u][0] = as[m0 * 32 + ((kk + lc) ^ sw)];
                a[u][1] = as[(m0 + 8) * 32 + ((kk + lc) ^ sw)];
                a[u][2] = as[m0 * 32 + ((kk + lc + 4) ^ sw)];
                a[u][3] = as[(m0 + 8) * 32 + ((kk + lc + 4) ^ sw)];
            }
#pragma unroll
            for (int j = 0; j < 8; j++) {
                const int n0 = wn + j * 8 + lr;
                const int kb = kk + lc;
                const int sw = (kb & 3) << 3;
                const uint32_t b0 = bs[kb * 128 + (n0 ^ sw)];
                const uint32_t b1 = bs[(kb + 4) * 128 + (n0 ^ sw)];
                MMA_TF32(c[0][j], a[0], b0, b1);
                MMA_TF32(c[1][j], a[1], b0, b1);
            }
        }

        if (kt + 1 < NK) {
            uint32_t* an = As + (cur ^ 1) * 4096;
            uint32_t* bnx = Bs + (cur ^ 1) * 4096;
#pragma unroll
            for (int i = 0; i < 4; i++) {
                const int idx = t + 256 * i;
                const int m = idx >> 3, k = (idx & 7) << 2;
                uint4 w = { f2tf32(pa[i].x), f2tf32(pa[i].y),
                            f2tf32(pa[i].z), f2tf32(pa[i].w) };
                *(uint4*)(an + m * 32 + (k ^ ((m & 7) << 2))) = w;
            }
#pragma unroll
            for (int i = 0; i < 4; i++) {
                const int idx = t + 256 * i;
                const int kk = idx >> 5, n = (idx & 31) << 2;
                uint4 w = { f2tf32(pb[i].x), f2tf32(pb[i].y),
                            f2tf32(pb[i].z), f2tf32(pb[i].w) };
                *(uint4*)(bnx + kk * 128 + (n ^ ((kk & 3) << 3))) = w;
            }
        }
        __syncthreads();
    }

#pragma unroll
    for (int u = 0; u < 2; u++) {
        const int row = bm + wm + u * 16 + lr;
#pragma unroll
        for (int j = 0; j < 8; j++) {
            const int col = bn + wn + j * 8 + 2 * lc;
            const float bx = __ldg(&bias[col]);
            const float by = __ldg(&bias[col + 1]);
            float2 v0 = { c[u][j][0] + bx, c[u][j][1] + by };
            float2 v1 = { c[u][j][2] + bx, c[u][j][3] + by };
            *(float2*)(C + (size_t)row * N + col)       = v0;
            *(float2*)(C + (size_t)(row + 8) * N + col) = v1;
        }
    }
}

// ===========================================================================
// Flash attention via mma.sync tf32.
// Block = (b, h, 128 Q rows), 256 threads / 8 warps; warp owns 16 Q rows.
// K-tiles of 64. SMEM (floats, stride 68 pads):
//   Ss [128][68] : Q staging -> S scores -> P (tf32-in-place)
//   Ks [ 64][68] : K tile (tf32), rows=key, cols=d  (= col-major B for QK^T)
//   Vt [ 64][68] : V^T tile (tf32), rows=d, cols=key (= col-major B for PV)
//   m/l/alpha [128] each
// ===========================================================================
#define ATS 68
#define OFF_KS (128 * ATS)
#define OFF_VT (OFF_KS + 64 * ATS)
#define OFF_M  (OFF_VT + 64 * ATS)
#define ATT_SMEM ((OFF_M + 3 * 128) * 4)

__global__ __launch_bounds__(256) void attn_mma_kernel(
    const float* __restrict__ qkv, float* __restrict__ outp)
{
    extern __shared__ float sm[];
    float*    Ss   = sm;
    uint32_t* Ps   = (uint32_t*)sm;
    uint32_t* Ks   = (uint32_t*)(sm + OFF_KS);
    uint32_t* Vt   = (uint32_t*)(sm + OFF_VT);
    float*    m_sh = sm + OFF_M;
    float*    l_sh = m_sh + 128;
    float*    a_sh = l_sh + 128;

    const int t    = threadIdx.x;
    const int lane = t & 31;
    const int lr   = lane >> 2;
    const int lc   = lane & 3;
    const int w    = t >> 5;
    const int wrow = w * 16;
    const int bh   = blockIdx.x;
    const int b    = bh >> 4, h = bh & 15;
    const int n0   = blockIdx.y * 128;

    const float* qbase = qkv + (size_t)(b * NSEQ + n0) * C3 + h * ND;
    const float* kbase = qkv + (size_t)(b * NSEQ) * C3 + NC + h * ND;
    const float* vbase = kbase + NC;

    // ---- stage Q (scaled by 1/8) into Ss: 2 threads/row, 32 floats each ----
    {
        const int r = t >> 1, c0 = (t & 1) * 32;
        const float* src = qbase + (size_t)r * C3 + c0;
#pragma unroll
        for (int i = 0; i < 8; i++) {
            float4 v = *(const float4*)(src + 4 * i);
            float* dst = Ss + r * ATS + c0 + 4 * i;
            dst[0] = v.x * 0.125f; dst[1] = v.y * 0.125f;
            dst[2] = v.z * 0.125f; dst[3] = v.w * 0.125f;
        }
    }
    if (t < 128) { m_sh[t] = -1e30f; l_sh[t] = 0.0f; }
    __syncthreads();

    // ---- Q A-frags (tf32), kept in registers ----
    uint32_t qf[8][4];
#pragma unroll
    for (int kc = 0; kc < 8; kc++) {
        qf[kc][0] = f2tf32(Ss[(wrow + lr) * ATS + 8 * kc + lc]);
        qf[kc][1] = f2tf32(Ss[(wrow + lr + 8) * ATS + 8 * kc + lc]);
        qf[kc][2] = f2tf32(Ss[(wrow + lr) * ATS + 8 * kc + lc + 4]);
        qf[kc][3] = f2tf32(Ss[(wrow + lr + 8) * ATS + 8 * kc + lc + 4]);
    }
    // (no sync needed: first overwrite of Ss happens after a later barrier)

    float o[8][4];
#pragma unroll
    for (int j = 0; j < 8; j++)
#pragma unroll
        for (int q = 0; q < 4; q++) o[j][q] = 0.0f;

    for (int kt = 0; kt < NSEQ; kt += 64) {
        // ---- load K tile + transposed V tile (tf32) ----
        {
            const int r = t >> 2, c0 = (t & 3) * 4;
            const float* ksrc = kbase + (size_t)(kt + r) * C3;
            const float* vsrc = vbase + (size_t)(kt + r) * C3;
#pragma unroll
            for (int i = 0; i < 4; i++) {
                const int c = c0 + 16 * i;
                float4 kv = *(const float4*)(ksrc + c);
                uint4 kw = { f2tf32(kv.x), f2tf32(kv.y), f2tf32(kv.z), f2tf32(kv.w) };
                *(uint4*)(Ks + r * ATS + c) = kw;
                float4 vv = *(const float4*)(vsrc + c);
                Vt[(c + 0) * ATS + r] = f2tf32(vv.x);
                Vt[(c + 1) * ATS + r] = f2tf32(vv.y);
                Vt[(c + 2) * ATS + r] = f2tf32(vv.z);
                Vt[(c + 3) * ATS + r] = f2tf32(vv.w);
            }
        }
        __syncthreads();

        // ---- S = Q @ K^T  (B[k][n] = K[n][k] = Ks[n][k], col-major native) ----
        float sacc[8][4];
#pragma unroll
        for (int j = 0; j < 8; j++)
#pragma unroll
            for (int q = 0; q < 4; q++) sacc[j][q] = 0.0f;

#pragma unroll
        for (int kc = 0; kc < 8; kc++) {
#pragma unroll
            for (int j = 0; j < 8; j++) {
                const uint32_t b0 = Ks[(j * 8 + lr) * ATS + 8 * kc + lc];
                const uint32_t b1 = Ks[(j * 8 + lr) * ATS + 8 * kc + lc + 4];
                MMA_TF32(sacc[j], qf[kc], b0, b1);
            }
        }

        // ---- store S frags to SMEM ----
#pragma unroll
        for (int j = 0; j < 8; j++) {
            float2 v0 = { sacc[j][0], sacc[j][1] };
            float2 v1 = { sacc[j][2], sacc[j][3] };
            *(float2*)&Ss[(wrow + lr) * ATS + 8 * j + 2 * lc]     = v0;
            *(float2*)&Ss[(wrow + lr + 8) * ATS + 8 * j + 2 * lc] = v1;
        }
        __syncthreads();

        // ---- online softmax: 2 threads/row, interleaved cols; P -> tf32 ----
        {
            const int r = t >> 1, q = t & 1;
            float* srow = Ss + r * ATS;
            const float mold = m_sh[r];
            float mx = mold;
#pragma unroll
            for (int i = 0; i < 32; i++)
                mx = fmaxf(mx, srow[q + 2 * i]);
            mx = fmaxf(mx, __shfl_xor_sync(0xffffffffu, mx, 1));
            float ls = 0.0f;
#pragma unroll
            for (int i = 0; i < 32; i++) {
                const float p = __expf(srow[q + 2 * i] - mx);
                ((uint32_t*)srow)[q + 2 * i] = f2tf32(p);
                ls += p;
            }
            ls += __shfl_xor_sync(0xffffffffu, ls, 1);
            if (q == 0) {
                const float al = __expf(mold - mx);
                l_sh[r] = l_sh[r] * al + ls;
                m_sh[r] = mx;
                a_sh[r] = al;
            }
        }
        __syncthreads();

        // ---- rescale O, then O += P @ V  (B = Vt[d][c], col-major native) ----
        {
            const float al0 = a_sh[wrow + lr];
            const float al1 = a_sh[wrow + lr + 8];
#pragma unroll
            for (int j = 0; j < 8; j++) {
                o[j][0] *= al0; o[j][1] *= al0;
                o[j][2] *= al1; o[j][3] *= al1;
            }
        }
#pragma unroll
        for (int kc = 0; kc < 8; kc++) {
            uint32_t pa[4];
            pa[0] = Ps[(wrow + lr) * ATS + 8 * kc + lc];
            pa[1] = Ps[(wrow + lr + 8) * ATS + 8 * kc + lc];
            pa[2] = Ps[(wrow + lr) * ATS + 8 * kc + lc + 4];
            pa[3] = Ps[(wrow + lr + 8) * ATS + 8 * kc + lc + 4];
#pragma unroll
            for (int j = 0; j < 8; j++) {
                const uint32_t b0 = Vt[(j * 8 + lr) * ATS + 8 * kc + lc];
                const uint32_t b1 = Vt[(j * 8 + lr) * ATS + 8 * kc + lc + 4];
                MMA_TF32(o[j], pa, b0, b1);
            }
        }
        __syncthreads();   // Ks/Vt/Ss reused next tile
    }

    // ---- epilogue: O /= l, write [B,N,H*D] ----
    {
        const float li0 = 1.0f / l_sh[wrow + lr];
        const float li1 = 1.0f / l_sh[wrow + lr + 8];
        const size_t row0 = (size_t)(b * NSEQ + n0 + wrow + lr) * NC + h * ND;
        const size_t row1 = row0 + (size_t)8 * NC;
#pragma unroll
        for (int j = 0; j < 8; j++) {
            const int col = 8 * j + 2 * lc;
            float2 v0 = { o[j][0] * li0, o[j][1] * li0 };
            float2 v1 = { o[j][2] * li1, o[j][3] * li1 };
            *(float2*)&outp[row0 + col] = v0;
            *(float2*)&outp[row1 + col] = v1;
        }
    }
}

// ---------------------------------------------------------------------------
extern "C" void kernel_launch(void* const* d_in, const int* in_sizes, int n_in,
                              void* d_out, int out_size)
{
    const float* x     = (const float*)d_in[0];
    const float* w_qkv = (const float*)d_in[1];
    const float* b_qkv = (const float*)d_in[2];
    const float* w_out = (const float*)d_in[3];
    const float* b_out = (const float*)d_in[4];
    float* out = (float*)d_out;

    float *qkvbuf = nullptr, *attnbuf = nullptr;
    cudaGetSymbolAddress((void**)&qkvbuf, g_qkv);
    cudaGetSymbolAddress((void**)&attnbuf, g_attn);

    cudaFuncSetAttribute(gemm_mma_kernel,
                         cudaFuncAttributeMaxDynamicSharedMemorySize, GEMM_SMEM);
    cudaFuncSetAttribute(attn_mma_kernel,
                         cudaFuncAttributeMaxDynamicSharedMemorySize, ATT_SMEM);

    // 1) qkv = x @ w_qkv + b_qkv
    {
        dim3 grid(C3 / GBN, NTOK / GBM);   // (24, 32)
        gemm_mma_kernel<<<grid, 256, GEMM_SMEM>>>(x, w_qkv, b_qkv, qkvbuf,
                                                  NTOK, C3, NC);
    }
    // 2) flash attention (mma tf32)
    {
        dim3 grid(NB * NH, NSEQ / 128);    // (32, 16)
        attn_mma_kernel<<<grid, 256, ATT_SMEM>>>(qkvbuf, attnbuf);
    }
    // 3) out = attn @ w_out + b_out
    {
        dim3 grid(NC / GBN, NTOK / GBM);   // (8, 32)
        gemm_mma_kernel<<<grid, 256, GEMM_SMEM>>>(attnbuf, w_out, b_out, out,
                                                  NTOK, NC, NC);
    }
}

// round 13
// speedup vs baseline: 6.2549x; 1.3392x over previous
#include <cuda_runtime.h>
#include <cuda_fp16.h>
#include <cstdint>

// ---------------------------------------------------------------------------
// MultiHeadSelfAttention: B=2, N=2048, C=1024, H=16, D=64, fp32 in/out.
// All three stages on fp16 HMMA (mma.sync m16n8k16, fp32 accumulate).
// fp16 RN conversion has the same epsilon (2^-11) as tf32 RNA.
// ---------------------------------------------------------------------------

#define NB    2
#define NSEQ  2048
#define NC    1024
#define NH    16
#define ND    64
#define NTOK  (NB * NSEQ)       // 4096
#define C3    (3 * NC)          // 3072

__device__ float g_qkv[NTOK * C3];      // 48 MiB
__device__ float g_attn[NTOK * NC];     // 16 MiB

// ---------------- helpers ----------------
__device__ __forceinline__ uint32_t h2pack(float lo, float hi) {
    uint32_t r;
    asm("cvt.rn.f16x2.f32 %0, %1, %2;" : "=r"(r) : "f"(hi), "f"(lo));
    return r;
}

#define MMA_F16(cc, aa, b0v, b1v)                                             \
    asm volatile("mma.sync.aligned.m16n8k16.row.col.f32.f16.f16.f32 "         \
                 "{%0,%1,%2,%3}, {%4,%5,%6,%7}, {%8,%9}, {%0,%1,%2,%3};"      \
                 : "+f"((cc)[0]), "+f"((cc)[1]), "+f"((cc)[2]), "+f"((cc)[3]) \
                 : "r"((aa)[0]), "r"((aa)[1]), "r"((aa)[2]), "r"((aa)[3]),    \
                   "r"(b0v), "r"(b1v))

// ===========================================================================
// GEMM fp16 HMMA:  C[M,N] = A[M,K] @ B[K,N] + bias[N]
// Block 128x128, BK=32 (2 k16 chunks), 256 threads / 8 warps (warp 32x64).
// SMEM (uints = f16x2), double buffered:
//   As[m][kk] stride 20 : h2(A[m][2kk], A[m][2kk+1])          (pairs along k)
//   Bs[kk2][n^((kk2&3)<<3)] stride 128 : h2(B[2kk2][n], B[2kk2+1][n])
// ===========================================================================
#define GBM 128
#define GBN 128
#define GBK 32
#define AST 20
#define AS_STAGE (128 * AST)     // 2560 uints
#define BS_STAGE (16 * 128)      // 2048 uints
#define GEMM_SMEM (2 * (AS_STAGE + BS_STAGE) * 4)

__global__ __launch_bounds__(256) void gemm_mma_kernel(
    const float* __restrict__ A, const float* __restrict__ B,
    const float* __restrict__ bias, float* __restrict__ C,
    int M, int N, int K)
{
    extern __shared__ uint32_t smu[];
    uint32_t* As = smu;                       // [2][AS_STAGE]
    uint32_t* Bs = smu + 2 * AS_STAGE;        // [2][BS_STAGE]

    const int t    = threadIdx.x;
    const int lane = t & 31;
    const int lr   = lane >> 2;
    const int lc   = lane & 3;
    const int wm   = ((t >> 5) & 3) * 32;
    const int wn   = (t >> 7) * 64;
    const int bm   = blockIdx.y * GBM;
    const int bn   = blockIdx.x * GBN;
    const int NK   = K / GBK;

    // staging maps
    const int am  = t >> 1;                 // 0..127 (A row)
    const int ak0 = (t & 1) * 16;           // A float-col base (16 floats)
    const int bk2 = t >> 4;                 // 0..15 (B h2 row = k pair)
    const int bn0 = (t & 15) * 8;           // B col base (8 cols)
    const int bsw = (bk2 & 3) << 3;

    float c[2][8][4];
#pragma unroll
    for (int u = 0; u < 2; u++)
#pragma unroll
        for (int j = 0; j < 8; j++)
#pragma unroll
            for (int q = 0; q < 4; q++) c[u][j][q] = 0.0f;

    // ---- stage chunk 0 ----
    {
        const float* ap = A + (size_t)(bm + am) * K + ak0;
#pragma unroll
        for (int i = 0; i < 2; i++) {
            float4 v0 = *(const float4*)(ap + 8 * i);
            float4 v1 = *(const float4*)(ap + 8 * i + 4);
            uint4 w = { h2pack(v0.x, v0.y), h2pack(v0.z, v0.w),
                        h2pack(v1.x, v1.y), h2pack(v1.z, v1.w) };
            *(uint4*)(As + am * AST + ak0 / 2 + 4 * i) = w;
        }
        const float* bp0 = B + (size_t)(2 * bk2) * N + bn + bn0;
        const float* bp1 = bp0 + N;
#pragma unroll
        for (int i = 0; i < 2; i++) {
            float4 u0 = *(const float4*)(bp0 + 4 * i);
            float4 u1 = *(const float4*)(bp1 + 4 * i);
            uint4 w = { h2pack(u0.x, u1.x), h2pack(u0.y, u1.y),
                        h2pack(u0.z, u1.z), h2pack(u0.w, u1.w) };
            *(uint4*)(Bs + bk2 * 128 + (bn0 ^ bsw) + 4 * i) = w;
        }
    }
    __syncthreads();

    for (int kt = 0; kt < NK; kt++) {
        const int cur = kt & 1;
        const uint32_t* as = As + cur * AS_STAGE;
        const uint32_t* bs = Bs + cur * BS_STAGE;

        // prefetch next chunk into regs
        float4 pa[4], pb[4];
        if (kt + 1 < NK) {
            const int kofs = (kt + 1) * GBK;
            const float* ap = A + (size_t)(bm + am) * K + kofs + ak0;
            pa[0] = *(const float4*)(ap);
            pa[1] = *(const float4*)(ap + 4);
            pa[2] = *(const float4*)(ap + 8);
            pa[3] = *(const float4*)(ap + 12);
            const float* bp0 = B + (size_t)(kofs + 2 * bk2) * N + bn + bn0;
            const float* bp1 = bp0 + N;
            pb[0] = *(const float4*)(bp0);
            pb[1] = *(const float4*)(bp0 + 4);
            pb[2] = *(const float4*)(bp1);
            pb[3] = *(const float4*)(bp1 + 4);
        }

        // ---- compute: 2 k16 chunks ----
#pragma unroll
        for (int kc = 0; kc < 2; kc++) {
            const int kk = 8 * kc + lc;
            uint32_t a[2][4];
#pragma unroll
            for (int u = 0; u < 2; u++) {
                const int m0 = wm + u * 16 + lr;
                a[u][0] = as[m0 * AST + kk];
                a[u][1] = as[(m0 + 8) * AST + kk];
                a[u][2] = as[m0 * AST + kk + 4];
                a[u][3] = as[(m0 + 8) * AST + kk + 4];
            }
            const int sw = (lc & 3) << 3;   // (8kc+lc)&3 == lc&3, same for +4
#pragma unroll
            for (int j = 0; j < 8; j++) {
                const int col = (wn + 8 * j + lr) ^ sw;
                const uint32_t b0 = bs[kk * 128 + col];
                const uint32_t b1 = bs[(kk + 4) * 128 + col];
                MMA_F16(c[0][j], a[0], b0, b1);
                MMA_F16(c[1][j], a[1], b0, b1);
            }
        }

        // ---- store prefetched chunk ----
        if (kt + 1 < NK) {
            uint32_t* an = As + (cur ^ 1) * AS_STAGE;
            uint32_t* bb = Bs + (cur ^ 1) * BS_STAGE;
#pragma unroll
            for (int i = 0; i < 2; i++) {
                float4 v0 = pa[2 * i], v1 = pa[2 * i + 1];
                uint4 w = { h2pack(v0.x, v0.y), h2pack(v0.z, v0.w),
                            h2pack(v1.x, v1.y), h2pack(v1.z, v1.w) };
                *(uint4*)(an + am * AST + ak0 / 2 + 4 * i) = w;
            }
#pragma unroll
            for (int i = 0; i < 2; i++) {
                float4 u0 = pb[i], u1 = pb[2 + i];
                uint4 w = { h2pack(u0.x, u1.x), h2pack(u0.y, u1.y),
                            h2pack(u0.z, u1.z), h2pack(u0.w, u1.w) };
                *(uint4*)(bb + bk2 * 128 + (bn0 ^ bsw) + 4 * i) = w;
            }
        }
        __syncthreads();
    }

    // ---- epilogue ----
#pragma unroll
    for (int u = 0; u < 2; u++) {
        const int row = bm + wm + u * 16 + lr;
#pragma unroll
        for (int j = 0; j < 8; j++) {
            const int col = bn + wn + j * 8 + 2 * lc;
            const float bx = __ldg(&bias[col]);
            const float by = __ldg(&bias[col + 1]);
            float2 v0 = { c[u][j][0] + bx, c[u][j][1] + by };
            float2 v1 = { c[u][j][2] + bx, c[u][j][3] + by };
            *(float2*)(C + (size_t)row * N + col)       = v0;
            *(float2*)(C + (size_t)(row + 8) * N + col) = v1;
        }
    }
}

// ===========================================================================
// Flash attention fp16 HMMA. Block = (b,h, 128 Q rows), 256 thr / 8 warps.
// K-tiles of 64. SMEM (uint units):
//   Qh/Ph [128][36] : h2 Q pairs-along-d -> later P pairs-along-key (overlaid)
//   Kt    [ 64][36] : h2(K[key][2d],K[key][2d+1])
//   Vt    [ 32][64] : h2(V[2kp][d],V[2kp+1][d]), col d ^ ((kp&3)<<3)
//   Ss f32[128][68] : S scores
//   m/l/a [128] each
// ===========================================================================
#define QHS 36
#define KTS 36
#define OFF_KT (128 * QHS)                 // 4608
#define OFF_VT (OFF_KT + 64 * KTS)         // 6912
#define OFF_SS (OFF_VT + 32 * 64)          // 8960
#define OFF_M  (OFF_SS + 128 * 68)         // 17664
#define ATT_SMEM ((OFF_M + 3 * 128) * 4)

__global__ __launch_bounds__(256) void attn_mma_kernel(
    const float* __restrict__ qkv, float* __restrict__ outp)
{
    extern __shared__ uint32_t smu[];
    uint32_t* Qh   = smu;
    uint16_t* Ph16 = (uint16_t*)smu;            // overlays Qh, stride 72 halves
    uint32_t* Kt   = smu + OFF_KT;
    uint32_t* Vt   = smu + OFF_VT;
    float*    Ss   = (float*)(smu + OFF_SS);
    float*    m_sh = (float*)(smu + OFF_M);
    float*    l_sh = m_sh + 128;
    float*    a_sh = l_sh + 128;

    const int t    = threadIdx.x;
    const int lane = t & 31;
    const int lr   = lane >> 2;
    const int lc   = lane & 3;
    const int w    = t >> 5;
    const int wrow = w * 16;
    const int bh   = blockIdx.x;
    const int b    = bh >> 4, h = bh & 15;
    const int n0   = blockIdx.y * 128;

    const float* qbase = qkv + (size_t)(b * NSEQ + n0) * C3 + h * ND;
    const float* kbase = qkv + (size_t)(b * NSEQ) * C3 + NC + h * ND;
    const float* vbase = kbase + NC;

    // ---- stage Q (scaled 1/8) as h2 pairs-along-d ----
    {
        const int r = t >> 1, c0 = (t & 1) * 32;
        const float* src = qbase + (size_t)r * C3 + c0;
#pragma unroll
        for (int i = 0; i < 4; i++) {
            float4 v0 = *(const float4*)(src + 8 * i);
            float4 v1 = *(const float4*)(src + 8 * i + 4);
            uint4 wq = { h2pack(v0.x * 0.125f, v0.y * 0.125f),
                         h2pack(v0.z * 0.125f, v0.w * 0.125f),
                         h2pack(v1.x * 0.125f, v1.y * 0.125f),
                         h2pack(v1.z * 0.125f, v1.w * 0.125f) };
            *(uint4*)(Qh + r * QHS + c0 / 2 + 4 * i) = wq;
        }
    }
    if (t < 128) { m_sh[t] = -1e30f; l_sh[t] = 0.0f; }
    __syncthreads();

    // ---- Q A-frags in registers: 4 k16 chunks ----
    uint32_t qf[4][4];
#pragma unroll
    for (int kc = 0; kc < 4; kc++) {
        const int kk = 8 * kc + lc;
        qf[kc][0] = Qh[(wrow + lr) * QHS + kk];
        qf[kc][1] = Qh[(wrow + lr + 8) * QHS + kk];
        qf[kc][2] = Qh[(wrow + lr) * QHS + kk + 4];
        qf[kc][3] = Qh[(wrow + lr + 8) * QHS + kk + 4];
    }

    float o[8][4];
#pragma unroll
    for (int j = 0; j < 8; j++)
#pragma unroll
        for (int q = 0; q < 4; q++) o[j][q] = 0.0f;

    for (int kt = 0; kt < NSEQ; kt += 64) {
        // ---- stage K tile: pairs along d, [key][dd] ----
        {
            const int r = t >> 2, c0 = (t & 3) * 16;
            const float* ksrc = kbase + (size_t)(kt + r) * C3 + c0;
#pragma unroll
            for (int i = 0; i < 2; i++) {
                float4 v0 = *(const float4*)(ksrc + 8 * i);
                float4 v1 = *(const float4*)(ksrc + 8 * i + 4);
                uint4 wk = { h2pack(v0.x, v0.y), h2pack(v0.z, v0.w),
                             h2pack(v1.x, v1.y), h2pack(v1.z, v1.w) };
                *(uint4*)(Kt + r * KTS + c0 / 2 + 4 * i) = wk;
            }
        }
        // ---- stage V tile: pairs along key, [kp][d^sw] ----
        {
            const int kp = t >> 3, d0 = (t & 7) * 8;
            const int sw = (kp & 3) << 3;
            const float* v0p = vbase + (size_t)(kt + 2 * kp) * C3 + d0;
            const float* v1p = v0p + C3;
            float4 u0 = *(const float4*)(v0p);
            float4 u1 = *(const float4*)(v0p + 4);
            float4 w0 = *(const float4*)(v1p);
            float4 w1 = *(const float4*)(v1p + 4);
            uint4 x0 = { h2pack(u0.x, w0.x), h2pack(u0.y, w0.y),
                         h2pack(u0.z, w0.z), h2pack(u0.w, w0.w) };
            uint4 x1 = { h2pack(u1.x, w1.x), h2pack(u1.y, w1.y),
                         h2pack(u1.z, w1.z), h2pack(u1.w, w1.w) };
            *(uint4*)(Vt + kp * 64 + (d0 ^ sw))     = x0;
            *(uint4*)(Vt + kp * 64 + (d0 ^ sw) + 4) = x1;
        }
        __syncthreads();

        // ---- S = Q @ K^T ----
        float sacc[8][4];
#pragma unroll
        for (int j = 0; j < 8; j++)
#pragma unroll
            for (int q = 0; q < 4; q++) sacc[j][q] = 0.0f;

#pragma unroll
        for (int kc = 0; kc < 4; kc++) {
            const int kk = 8 * kc + lc;
#pragma unroll
            for (int j = 0; j < 8; j++) {
                const uint32_t b0 = Kt[(8 * j + lr) * KTS + kk];
                const uint32_t b1 = Kt[(8 * j + lr) * KTS + kk + 4];
                MMA_F16(sacc[j], qf[kc], b0, b1);
            }
        }

        // ---- store S (f32) ----
#pragma unroll
        for (int j = 0; j < 8; j++) {
            float2 v0 = { sacc[j][0], sacc[j][1] };
            float2 v1 = { sacc[j][2], sacc[j][3] };
            *(float2*)&Ss[(wrow + lr) * 68 + 8 * j + 2 * lc]     = v0;
            *(float2*)&Ss[(wrow + lr + 8) * 68 + 8 * j + 2 * lc] = v1;
        }
        __syncthreads();

        // ---- online softmax: 2 thr/row; write P as fp16 into Ph ----
        {
            const int r = t >> 1, q = t & 1;
            const float* srow = Ss + r * 68;
            uint16_t* prow = Ph16 + r * 72;
            const float mold = m_sh[r];
            float mx = mold;
#pragma unroll
            for (int i = 0; i < 32; i++)
                mx = fmaxf(mx, srow[q + 2 * i]);
            mx = fmaxf(mx, __shfl_xor_sync(0xffffffffu, mx, 1));
            float ls = 0.0f;
#pragma unroll
            for (int i = 0; i < 32; i++) {
                const float p = __expf(srow[q + 2 * i] - mx);
                prow[q + 2 * i] = __half_as_ushort(__float2half_rn(p));
                ls += p;
            }
            ls += __shfl_xor_sync(0xffffffffu, ls, 1);
            if (q == 0) {
                const float al = __expf(mold - mx);
                l_sh[r] = l_sh[r] * al + ls;
                m_sh[r] = mx;
                a_sh[r] = al;
            }
        }
        __syncthreads();

        // ---- rescale O; O += P @ V ----
        {
            const float al0 = a_sh[wrow + lr];
            const float al1 = a_sh[wrow + lr + 8];
#pragma unroll
            for (int j = 0; j < 8; j++) {
                o[j][0] *= al0; o[j][1] *= al0;
                o[j][2] *= al1; o[j][3] *= al1;
            }
        }
#pragma unroll
        for (int kc = 0; kc < 4; kc++) {
            const int kk = 8 * kc + lc;
            uint32_t pa[4];
            pa[0] = Qh[(wrow + lr) * QHS + kk];        // Ph overlays Qh
            pa[1] = Qh[(wrow + lr + 8) * QHS + kk];
            pa[2] = Qh[(wrow + lr) * QHS + kk + 4];
            pa[3] = Qh[(wrow + lr + 8) * QHS + kk + 4];
            const int sw = (lc & 3) << 3;
#pragma unroll
            for (int j = 0; j < 8; j++) {
                const int col = (8 * j + lr) ^ sw;
                const uint32_t b0 = Vt[kk * 64 + col];
                const uint32_t b1 = Vt[(kk + 4) * 64 + col];
                MMA_F16(o[j], pa, b0, b1);
            }
        }
        __syncthreads();
    }

    // ---- epilogue: O /= l, write [B,N,H*D] ----
    {
        const float li0 = 1.0f / l_sh[wrow + lr];
        const float li1 = 1.0f / l_sh[wrow + lr + 8];
        const size_t row0 = (size_t)(b * NSEQ + n0 + wrow + lr) * NC + h * ND;
        const size_t row1 = row0 + (size_t)8 * NC;
#pragma unroll
        for (int j = 0; j < 8; j++) {
            const int col = 8 * j + 2 * lc;
            float2 v0 = { o[j][0] * li0, o[j][1] * li0 };
            float2 v1 = { o[j][2] * li1, o[j][3] * li1 };
            *(float2*)&outp[row0 + col] = v0;
            *(float2*)&outp[row1 + col] = v1;
        }
    }
}

// ---------------------------------------------------------------------------
extern "C" void kernel_launch(void* const* d_in, const int* in_sizes, int n_in,
                              void* d_out, int out_size)
{
    const float* x     = (const float*)d_in[0];
    const float* w_qkv = (const float*)d_in[1];
    const float* b_qkv = (const float*)d_in[2];
    const float* w_out = (const float*)d_in[3];
    const float* b_out = (const float*)d_in[4];
    float* out = (float*)d_out;

    float *qkvbuf = nullptr, *attnbuf = nullptr;
    cudaGetSymbolAddress((void**)&qkvbuf, g_qkv);
    cudaGetSymbolAddress((void**)&attnbuf, g_attn);

    cudaFuncSetAttribute(gemm_mma_kernel,
                         cudaFuncAttributeMaxDynamicSharedMemorySize, GEMM_SMEM);
    cudaFuncSetAttribute(attn_mma_kernel,
                         cudaFuncAttributeMaxDynamicSharedMemorySize, ATT_SMEM);

    // 1) qkv = x @ w_qkv + b_qkv
    {
        dim3 grid(C3 / GBN, NTOK / GBM);   // (24, 32)
        gemm_mma_kernel<<<grid, 256, GEMM_SMEM>>>(x, w_qkv, b_qkv, qkvbuf,
                                                  NTOK, C3, NC);
    }
    // 2) flash attention (fp16 HMMA)
    {
        dim3 grid(NB * NH, NSEQ / 128);    // (32, 16)
        attn_mma_kernel<<<grid, 256, ATT_SMEM>>>(qkvbuf, attnbuf);
    }
    // 3) out = attn @ w_out + b_out
    {
        dim3 grid(NC / GBN, NTOK / GBM);   // (8, 32)
        gemm_mma_kernel<<<grid, 256, GEMM_SMEM>>>(attnbuf, w_out, b_out, out,
                                                  NTOK, NC, NC);
    }
}

// round 14
// speedup vs baseline: 7.6903x; 1.2295x over previous
#include <cuda_runtime.h>
#include <cuda_fp16.h>
#include <cstdint>

// ---------------------------------------------------------------------------
// MultiHeadSelfAttention: B=2, N=2048, C=1024, H=16, D=64, fp32 in/out.
// Pipeline (all tensor work on fp16 HMMA mma.sync m16n8k16, fp32 accum):
//   prep:  x->fp16, w_qkv->fp16 [N][K], w_out->fp16 [N][K]
//   gemm1: qkv_h = xh @ wqkvT^T + b      (fp16 out)
//   attn:  flash attention fp16 in/out
//   gemm3: out = attnh @ woutT^T + b     (fp32 out)
// Hot loops: cp.async staging + ldmatrix fragment loads only.
// ---------------------------------------------------------------------------

#define NB    2
#define NSEQ  2048
#define NC    1024
#define NH    16
#define ND    64
#define NTOK  (NB * NSEQ)       // 4096
#define C3    (3 * NC)          // 3072

__device__ __half g_xh[NTOK * NC];        //  8 MiB
__device__ __half g_qkvh[NTOK * C3];      // 24 MiB
__device__ __half g_attnh[NTOK * NC];     //  8 MiB
__device__ __half g_wqkvT[C3 * NC];       //  6 MiB  [3072][1024]
__device__ __half g_woutT[NC * NC];       //  2 MiB  [1024][1024]

// ---------------- helpers ----------------
__device__ __forceinline__ uint32_t smem_u32(const void* p) {
    uint32_t a;
    asm("{ .reg .u64 t; cvta.to.shared.u64 t, %1; cvt.u32.u64 %0, t; }"
        : "=r"(a) : "l"(p));
    return a;
}
__device__ __forceinline__ uint32_t h2pack(float lo, float hi) {
    uint32_t r;
    asm("cvt.rn.f16x2.f32 %0, %1, %2;" : "=r"(r) : "f"(hi), "f"(lo));
    return r;
}

#define MMA_F16(cc, aa, b0v, b1v)                                             \
    asm volatile("mma.sync.aligned.m16n8k16.row.col.f32.f16.f16.f32 "         \
                 "{%0,%1,%2,%3}, {%4,%5,%6,%7}, {%8,%9}, {%0,%1,%2,%3};"      \
                 : "+f"((cc)[0]), "+f"((cc)[1]), "+f"((cc)[2]), "+f"((cc)[3]) \
                 : "r"((aa)[0]), "r"((aa)[1]), "r"((aa)[2]), "r"((aa)[3]),    \
                   "r"(b0v), "r"(b1v))

#define LDSM4(R, addr)                                                        \
    asm volatile("ldmatrix.sync.aligned.m8n8.x4.shared.b16 {%0,%1,%2,%3}, [%4];" \
                 : "=r"((R)[0]), "=r"((R)[1]), "=r"((R)[2]), "=r"((R)[3])     \
                 : "r"(addr))

#define CP16(dst, src)                                                        \
    asm volatile("cp.async.cg.shared.global [%0], [%1], 16;"                  \
                 :: "r"(dst), "l"(src) : "memory")
#define CP_COMMIT() asm volatile("cp.async.commit_group;" ::: "memory")
#define CP_WAIT(n)  asm volatile("cp.async.wait_group %0;" :: "n"(n) : "memory")

// ===========================================================================
// Prep kernels
// ===========================================================================
__global__ __launch_bounds__(256) void cvt_x_kernel(
    const float* __restrict__ in, __half* __restrict__ out)
{
    const int i = (blockIdx.x * 256 + threadIdx.x) * 4;
    float4 v = *(const float4*)(in + i);
    uint2 w = { h2pack(v.x, v.y), h2pack(v.z, v.w) };
    *(uint2*)((uint16_t*)out + i) = w;
}

// in fp32 [R][Cc]  ->  out fp16 [Cc][R]
__global__ void wT_kernel(const float* __restrict__ in,
                          __half* __restrict__ out, int R, int Cc)
{
    __shared__ float tile[32][33];
    const int c0 = blockIdx.x * 32, r0 = blockIdx.y * 32;
#pragma unroll
    for (int i = threadIdx.y; i < 32; i += 8)
        tile[i][threadIdx.x] = in[(size_t)(r0 + i) * Cc + c0 + threadIdx.x];
    __syncthreads();
#pragma unroll
    for (int i = threadIdx.y; i < 32; i += 8)
        out[(size_t)(c0 + i) * R + r0 + threadIdx.x] =
            __float2half_rn(tile[threadIdx.x][i]);
}

// ===========================================================================
// GEMM fp16:  C[M,N] = A[M,K] @ BT[N,K]^T + bias ;  out fp32 or fp16.
// Block 128x128, BK=32, 256 thr / 8 warps (warp 32x64).
// SMEM uint4: A stage s at s*512, B stage s at 1024+s*512 (32 KB total).
// Tile rows = 64B = 4 chunks, chunk col swizzle c ^ ((row&7)>>1).
// ===========================================================================
#define GEMM_SMEM (2048 * 16)

__global__ __launch_bounds__(256) void gemm16_kernel(
    const __half* __restrict__ Ah, const __half* __restrict__ BT,
    const float* __restrict__ bias, float* __restrict__ Cf,
    __half* __restrict__ Ch, int M, int N, int K)
{
    extern __shared__ uint4 smq[];
    const uint32_t smb = smem_u32(smq);

    const int t    = threadIdx.x;
    const int lane = t & 31;
    const int lr   = lane >> 2;
    const int lc   = lane & 3;
    const int wm   = ((t >> 5) & 3) * 32;
    const int wn   = (t >> 7) * 64;
    const int bm   = blockIdx.y * 128;
    const int bn   = blockIdx.x * 128;
    const int NK   = K / 32;

    // staging map: thread -> row stm, chunks stc, stc+1
    const int stm = t >> 1;
    const int stc = (t & 1) * 2;
    const int ssw = (stm & 7) >> 1;
    const __half* arow = Ah + (size_t)(bm + stm) * K + stc * 8;
    const __half* brow = BT + (size_t)(bn + stm) * K + stc * 8;
    const uint32_t adst0 = smb + (stm * 4 + (stc ^ ssw)) * 16;
    const uint32_t adst1 = smb + (stm * 4 + ((stc + 1) ^ ssw)) * 16;
    const uint32_t bdst0 = adst0 + 1024 * 16;
    const uint32_t bdst1 = adst1 + 1024 * 16;

    // fragment address components
    const int fr  = lane & 7;
    const int fg1 = (lane >> 3) & 1;
    const int fg2 = lane >> 4;
    const int rowA0 = wm + fr + fg1 * 8;         // + u*16
    const int swA   = (rowA0 & 7) >> 1;
    const int rowB0 = wn + fr + fg2 * 8;         // + jp*16
    const int swB   = (rowB0 & 7) >> 1;
    const int cAa   = fg2;                        // + 2*kc
    const int cBb   = fg1;                        // + 2*kc

    float c[2][8][4];
#pragma unroll
    for (int u = 0; u < 2; u++)
#pragma unroll
        for (int j = 0; j < 8; j++)
#pragma unroll
            for (int q = 0; q < 4; q++) c[u][j][q] = 0.0f;

    // stage chunk 0
    CP16(adst0, arow); CP16(adst1, arow + 8);
    CP16(bdst0, brow); CP16(bdst1, brow + 8);
    CP_COMMIT();

    for (int kt = 0; kt < NK; kt++) {
        if (kt + 1 < NK) {
            const int s = (kt + 1) & 1;
            const int ko = (kt + 1) * 32;
            CP16(adst0 + s * 512 * 16, arow + ko);
            CP16(adst1 + s * 512 * 16, arow + ko + 8);
            CP16(bdst0 + s * 512 * 16, brow + ko);
            CP16(bdst1 + s * 512 * 16, brow + ko + 8);
            CP_COMMIT();
            CP_WAIT(1);
        } else {
            CP_WAIT(0);
        }
        __syncthreads();

        const uint32_t abase = smb + ((kt & 1) * 512) * 16;
        const uint32_t bbase = abase + 1024 * 16;

#pragma unroll
        for (int kc = 0; kc < 2; kc++) {
            uint32_t a[2][4];
#pragma unroll
            for (int u = 0; u < 2; u++) {
                const uint32_t ad = abase +
                    ((rowA0 + u * 16) * 4 + ((2 * kc + cAa) ^ swA)) * 16;
                LDSM4(a[u], ad);
            }
#pragma unroll
            for (int jp = 0; jp < 4; jp++) {
                uint32_t bb[4];
                const uint32_t bd = bbase +
                    ((rowB0 + jp * 16) * 4 + ((2 * kc + cBb) ^ swB)) * 16;
                LDSM4(bb, bd);
                MMA_F16(c[0][2 * jp],     a[0], bb[0], bb[1]);
                MMA_F16(c[1][2 * jp],     a[1], bb[0], bb[1]);
                MMA_F16(c[0][2 * jp + 1], a[0], bb[2], bb[3]);
                MMA_F16(c[1][2 * jp + 1], a[1], bb[2], bb[3]);
            }
        }
        __syncthreads();
    }

    // ---- epilogue ----
#pragma unroll
    for (int u = 0; u < 2; u++) {
        const int row = bm + wm + u * 16 + lr;
#pragma unroll
        for (int j = 0; j < 8; j++) {
            const int col = bn + wn + j * 8 + 2 * lc;
            const float bx = __ldg(&bias[col]);
            const float by = __ldg(&bias[col + 1]);
            const float v00 = c[u][j][0] + bx, v01 = c[u][j][1] + by;
            const float v10 = c[u][j][2] + bx, v11 = c[u][j][3] + by;
            if (Ch) {
                *(uint32_t*)((uint16_t*)Ch + (size_t)row * N + col) =
                    h2pack(v00, v01);
                *(uint32_t*)((uint16_t*)Ch + (size_t)(row + 8) * N + col) =
                    h2pack(v10, v11);
            } else {
                float2 w0 = { v00, v01 }, w1 = { v10, v11 };
                *(float2*)(Cf + (size_t)row * N + col)       = w0;
                *(float2*)(Cf + (size_t)(row + 8) * N + col) = w1;
            }
        }
    }
}

// ===========================================================================
// Flash attention fp16 in/out. Block = (b,h, 128 Q rows), 256 thr / 8 warps.
// SMEM: Qs uint4[128][8] (swz c^(r&7)), Ks uint4[64][8], Vt uint[32][64]
// (packed key-pairs, d ^ ((k2&3)<<3)), Ss f32[128][68] (P fp16 in place).
// ===========================================================================
#define KSB4 1024                 // Ks base, uint4 units
#define VTB  6144                 // Vt base, uint units
#define SSB  8192                 // Ss base, float units
#define MSB  (SSB + 128 * 68)     // 16896
#define ATT_SMEM ((MSB + 3 * 128) * 4)

__global__ __launch_bounds__(256) void attn16_kernel(
    const __half* __restrict__ qkvh, __half* __restrict__ outh)
{
    extern __shared__ uint4 smq[];
    const uint32_t smb = smem_u32(smq);
    uint32_t* VtU  = (uint32_t*)smq + VTB;
    float*    Ss   = (float*)smq + SSB;
    float*    m_sh = (float*)smq + MSB;
    float*    l_sh = m_sh + 128;
    float*    a_sh = l_sh + 128;

    const int t    = threadIdx.x;
    const int lane = t & 31;
    const int lr   = lane >> 2;
    const int lc   = lane & 3;
    const int w    = t >> 5;
    const int wrow = w * 16;
    const int bh   = blockIdx.x;
    const int b    = bh >> 4, h = bh & 15;
    const int n0   = blockIdx.y * 128;

    const uint16_t* qkv16 = (const uint16_t*)qkvh;
    const uint16_t* qb = qkv16 + (size_t)(b * NSEQ + n0) * C3 + h * ND;
    const uint16_t* kb = qkv16 + (size_t)(b * NSEQ) * C3 + NC + h * ND;
    const uint16_t* vb = kb + NC;

    // fragment components
    const int fr  = lane & 7;
    const int fg1 = (lane >> 3) & 1;
    const int fg2 = lane >> 4;

    // ---- stage Q via cp.async: 4 chunks/thread ----
    {
        const int qm = t >> 1, qc0 = (t & 1) * 4;
        const uint16_t* src = qb + (size_t)qm * C3 + qc0 * 8;
#pragma unroll
        for (int i = 0; i < 4; i++) {
            const int cc = qc0 + i;
            CP16(smb + (qm * 8 + (cc ^ (qm & 7))) * 16, src + i * 8);
        }
        CP_COMMIT();
    }
    if (t < 128) { m_sh[t] = -1e30f; l_sh[t] = 0.0f; }
    CP_WAIT(0);
    __syncthreads();

    // ---- Q frags (scale folded later into softmax? no: fold via S scale) ----
    // We fold 1/8 into exp argument instead (scale S when reading for softmax
    // would add work) -> instead scale Q frags here is impossible (fp16 regs).
    // Use scale at softmax: S*0.125 during max/exp (2 extra mul per element).
    uint32_t qf[4][4];
#pragma unroll
    for (int kc = 0; kc < 4; kc++) {
        const int rowQ = wrow + fr + fg1 * 8;
        const int cQ = 2 * kc + fg2;
        LDSM4(qf[kc], smb + (rowQ * 8 + (cQ ^ (rowQ & 7))) * 16);
    }

    float o[8][4];
#pragma unroll
    for (int j = 0; j < 8; j++)
#pragma unroll
        for (int q = 0; q < 4; q++) o[j][q] = 0.0f;

    for (int kt = 0; kt < NSEQ; kt += 64) {
        // ---- stage K via cp.async ----
        {
            const int kr = t >> 2, kc0 = 2 * (t & 3);
            const uint16_t* src = kb + (size_t)(kt + kr) * C3 + kc0 * 8;
#pragma unroll
            for (int i = 0; i < 2; i++) {
                const int cc = kc0 + i;
                CP16(smb + (KSB4 + kr * 8 + (cc ^ (kr & 7))) * 16, src + i * 8);
            }
            CP_COMMIT();
        }
        // ---- stage V manually (packed key-pairs) ----
        {
            const int kp = t >> 3, d0 = (t & 7) * 8;
            const int sw = (kp & 3) << 3;
            const uint4 u0 = *(const uint4*)(vb + (size_t)(kt + 2 * kp) * C3 + d0);
            const uint4 u1 = *(const uint4*)(vb + (size_t)(kt + 2 * kp + 1) * C3 + d0);
            uint4 x0 = { __byte_perm(u0.x, u1.x, 0x5410),
                         __byte_perm(u0.x, u1.x, 0x7632),
                         __byte_perm(u0.y, u1.y, 0x5410),
                         __byte_perm(u0.y, u1.y, 0x7632) };
            uint4 x1 = { __byte_perm(u0.z, u1.z, 0x5410),
                         __byte_perm(u0.z, u1.z, 0x7632),
                         __byte_perm(u0.w, u1.w, 0x5410),
                         __byte_perm(u0.w, u1.w, 0x7632) };
            *(uint4*)(VtU + kp * 64 + (d0 ^ sw))     = x0;
            *(uint4*)(VtU + kp * 64 + (d0 ^ sw) + 4) = x1;
        }
        CP_WAIT(0);
        __syncthreads();

        // ---- S = Q @ K^T ----
        float sacc[8][4];
#pragma unroll
        for (int j = 0; j < 8; j++)
#pragma unroll
            for (int q = 0; q < 4; q++) sacc[j][q] = 0.0f;

#pragma unroll
        for (int kc = 0; kc < 4; kc++) {
#pragma unroll
            for (int jp = 0; jp < 4; jp++) {
                uint32_t bb[4];
                const int rowK = jp * 16 + fr + fg2 * 8;
                const int cK = 2 * kc + fg1;
                LDSM4(bb, smb + (KSB4 + rowK * 8 + (cK ^ (rowK & 7))) * 16);
                MMA_F16(sacc[2 * jp],     qf[kc], bb[0], bb[1]);
                MMA_F16(sacc[2 * jp + 1], qf[kc], bb[2], bb[3]);
            }
        }

        // ---- store S ----
#pragma unroll
        for (int j = 0; j < 8; j++) {
            float2 v0 = { sacc[j][0], sacc[j][1] };
            float2 v1 = { sacc[j][2], sacc[j][3] };
            *(float2*)&Ss[(wrow + lr) * 68 + 8 * j + 2 * lc]     = v0;
            *(float2*)&Ss[(wrow + lr + 8) * 68 + 8 * j + 2 * lc] = v1;
        }
        __syncthreads();

        // ---- online softmax (scale 1/8); P fp16 written in place ----
        {
            const int r = t >> 1, q = t & 1;
            float* srow = Ss + r * 68;
            uint16_t* prow = (uint16_t*)srow;
            const float mold = m_sh[r];
            float mx = mold;
#pragma unroll
            for (int i = 0; i < 32; i++)
                mx = fmaxf(mx, srow[q + 2 * i] * 0.125f);
            mx = fmaxf(mx, __shfl_xor_sync(0xffffffffu, mx, 1));
            float ls = 0.0f;
#pragma unroll
            for (int i = 0; i < 32; i++) {
                const float p = __expf(srow[q + 2 * i] * 0.125f - mx);
                prow[q + 2 * i] = __half_as_ushort(__float2half_rn(p));
                ls += p;
            }
            ls += __shfl_xor_sync(0xffffffffu, ls, 1);
            if (q == 0) {
                const float al = __expf(mold - mx);
                l_sh[r] = l_sh[r] * al + ls;
                m_sh[r] = mx;
                a_sh[r] = al;
            }
        }
        __syncthreads();

        // ---- rescale O ; O += P @ V ----
        {
            const float al0 = a_sh[wrow + lr];
            const float al1 = a_sh[wrow + lr + 8];
#pragma unroll
            for (int j = 0; j < 8; j++) {
                o[j][0] *= al0; o[j][1] *= al0;
                o[j][2] *= al1; o[j][3] *= al1;
            }
        }
#pragma unroll
        for (int kc = 0; kc < 4; kc++) {
            uint32_t pa[4];
            const int rowP = wrow + fr + fg1 * 8;
            LDSM4(pa, smb + (SSB + rowP * 68 + 8 * kc + fg2 * 4) * 4);
            const int kk = 8 * kc + lc;
            const int sw = (lc & 3) << 3;
#pragma unroll
            for (int j = 0; j < 8; j++) {
                const int col = (8 * j + lr) ^ sw;
                const uint32_t b0 = VtU[kk * 64 + col];
                const uint32_t b1 = VtU[(kk + 4) * 64 + col];
                MMA_F16(o[j], pa, b0, b1);
            }
        }
        __syncthreads();
    }

    // ---- epilogue: O /= l, fp16 out [B,N,H*D] ----
    {
        const float li0 = 1.0f / l_sh[wrow + lr];
        const float li1 = 1.0f / l_sh[wrow + lr + 8];
        uint16_t* ob = (uint16_t*)outh;
        const size_t r0 = (size_t)(b * NSEQ + n0 + wrow + lr) * NC + h * ND;
        const size_t r1 = r0 + (size_t)8 * NC;
#pragma unroll
        for (int j = 0; j < 8; j++) {
            const int col = 8 * j + 2 * lc;
            *(uint32_t*)(ob + r0 + col) = h2pack(o[j][0] * li0, o[j][1] * li0);
            *(uint32_t*)(ob + r1 + col) = h2pack(o[j][2] * li1, o[j][3] * li1);
        }
    }
}

// ---------------------------------------------------------------------------
extern "C" void kernel_launch(void* const* d_in, const int* in_sizes, int n_in,
                              void* d_out, int out_size)
{
    const float* x     = (const float*)d_in[0];
    const float* w_qkv = (const float*)d_in[1];
    const float* b_qkv = (const float*)d_in[2];
    const float* w_out = (const float*)d_in[3];
    const float* b_out = (const float*)d_in[4];
    float* out = (float*)d_out;

    __half *xh, *qkvh, *attnh, *wqkvT, *woutT;
    cudaGetSymbolAddress((void**)&xh, g_xh);
    cudaGetSymbolAddress((void**)&qkvh, g_qkvh);
    cudaGetSymbolAddress((void**)&attnh, g_attnh);
    cudaGetSymbolAddress((void**)&wqkvT, g_wqkvT);
    cudaGetSymbolAddress((void**)&woutT, g_woutT);

    cudaFuncSetAttribute(gemm16_kernel,
                         cudaFuncAttributeMaxDynamicSharedMemorySize, GEMM_SMEM);
    cudaFuncSetAttribute(attn16_kernel,
                         cudaFuncAttributeMaxDynamicSharedMemorySize, ATT_SMEM);

    // 0) prep: conversions + weight transposes
    cvt_x_kernel<<<NTOK * NC / 1024, 256>>>(x, xh);
    {
        dim3 blk(32, 8);
        dim3 g1(C3 / 32, NC / 32);
        wT_kernel<<<g1, blk>>>(w_qkv, wqkvT, NC, C3);
        dim3 g2(NC / 32, NC / 32);
        wT_kernel<<<g2, blk>>>(w_out, woutT, NC, NC);
    }
    // 1) qkv = x @ w_qkv + b_qkv   (fp16 out)
    {
        dim3 grid(C3 / 128, NTOK / 128);   // (24, 32)
        gemm16_kernel<<<grid, 256, GEMM_SMEM>>>(xh, wqkvT, b_qkv,
                                                nullptr, qkvh, NTOK, C3, NC);
    }
    // 2) flash attention
    {
        dim3 grid(NB * NH, NSEQ / 128);    // (32, 16)
        attn16_kernel<<<grid, 256, ATT_SMEM>>>(qkvh, attnh);
    }
    // 3) out = attn @ w_out + b_out (fp32 out)
    {
        dim3 grid(NC / 128, NTOK / 128);   // (8, 32)
        gemm16_kernel<<<grid, 256, GEMM_SMEM>>>(attnh, woutT, b_out,
                                                out, nullptr, NTOK, NC, NC);
    }
}

// round 15
// speedup vs baseline: 10.8869x; 1.4157x over previous
#include <cuda_runtime.h>
#include <cuda_fp16.h>
#include <cstdint>

// ---------------------------------------------------------------------------
// MultiHeadSelfAttention: B=2, N=2048, C=1024, H=16, D=64, fp32 in/out.
//   prep:  x->fp16, w_qkv->fp16 [N][K], w_out->fp16 [N][K]
//   gemm1: qkv_h = xh @ wqkvT^T + b      (fp16 out)
//   attn:  flash attention, fp16 HMMA, register-resident softmax (FA2)
//   gemm3: out = attnh @ woutT^T + b     (fp32 out)
// ---------------------------------------------------------------------------

#define NB    2
#define NSEQ  2048
#define NC    1024
#define NH    16
#define ND    64
#define NTOK  (NB * NSEQ)       // 4096
#define C3    (3 * NC)          // 3072

__device__ __half g_xh[NTOK * NC];
__device__ __half g_qkvh[NTOK * C3];
__device__ __half g_attnh[NTOK * NC];
__device__ __half g_wqkvT[C3 * NC];
__device__ __half g_woutT[NC * NC];

// ---------------- helpers ----------------
__device__ __forceinline__ uint32_t smem_u32(const void* p) {
    uint32_t a;
    asm("{ .reg .u64 t; cvta.to.shared.u64 t, %1; cvt.u32.u64 %0, t; }"
        : "=r"(a) : "l"(p));
    return a;
}
__device__ __forceinline__ uint32_t h2pack(float lo, float hi) {
    uint32_t r;
    asm("cvt.rn.f16x2.f32 %0, %1, %2;" : "=r"(r) : "f"(hi), "f"(lo));
    return r;
}

#define MMA_F16(cc, aa, b0v, b1v)                                             \
    asm volatile("mma.sync.aligned.m16n8k16.row.col.f32.f16.f16.f32 "         \
                 "{%0,%1,%2,%3}, {%4,%5,%6,%7}, {%8,%9}, {%0,%1,%2,%3};"      \
                 : "+f"((cc)[0]), "+f"((cc)[1]), "+f"((cc)[2]), "+f"((cc)[3]) \
                 : "r"((aa)[0]), "r"((aa)[1]), "r"((aa)[2]), "r"((aa)[3]),    \
                   "r"(b0v), "r"(b1v))

#define LDSM4(R, addr)                                                        \
    asm volatile("ldmatrix.sync.aligned.m8n8.x4.shared.b16 {%0,%1,%2,%3}, [%4];" \
                 : "=r"((R)[0]), "=r"((R)[1]), "=r"((R)[2]), "=r"((R)[3])     \
                 : "r"(addr))

#define CP16(dst, src)                                                        \
    asm volatile("cp.async.cg.shared.global [%0], [%1], 16;"                  \
                 :: "r"(dst), "l"(src) : "memory")
#define CP_COMMIT() asm volatile("cp.async.commit_group;" ::: "memory")
#define CP_WAIT(n)  asm volatile("cp.async.wait_group %0;" :: "n"(n) : "memory")

// ===========================================================================
// Prep kernels
// ===========================================================================
__global__ __launch_bounds__(256) void cvt_x_kernel(
    const float* __restrict__ in, __half* __restrict__ out)
{
    const int i = (blockIdx.x * 256 + threadIdx.x) * 4;
    float4 v = *(const float4*)(in + i);
    uint2 w = { h2pack(v.x, v.y), h2pack(v.z, v.w) };
    *(uint2*)((uint16_t*)out + i) = w;
}

__global__ void wT_kernel(const float* __restrict__ in,
                          __half* __restrict__ out, int R, int Cc)
{
    __shared__ float tile[32][33];
    const int c0 = blockIdx.x * 32, r0 = blockIdx.y * 32;
#pragma unroll
    for (int i = threadIdx.y; i < 32; i += 8)
        tile[i][threadIdx.x] = in[(size_t)(r0 + i) * Cc + c0 + threadIdx.x];
    __syncthreads();
#pragma unroll
    for (int i = threadIdx.y; i < 32; i += 8)
        out[(size_t)(c0 + i) * R + r0 + threadIdx.x] =
            __float2half_rn(tile[threadIdx.x][i]);
}

// ===========================================================================
// GEMM fp16 (unchanged from R14 — validated).
// ===========================================================================
#define GEMM_SMEM (2048 * 16)

__global__ __launch_bounds__(256) void gemm16_kernel(
    const __half* __restrict__ Ah, const __half* __restrict__ BT,
    const float* __restrict__ bias, float* __restrict__ Cf,
    __half* __restrict__ Ch, int M, int N, int K)
{
    extern __shared__ uint4 smq[];
    const uint32_t smb = smem_u32(smq);

    const int t    = threadIdx.x;
    const int lane = t & 31;
    const int lr   = lane >> 2;
    const int lc   = lane & 3;
    const int wm   = ((t >> 5) & 3) * 32;
    const int wn   = (t >> 7) * 64;
    const int bm   = blockIdx.y * 128;
    const int bn   = blockIdx.x * 128;
    const int NK   = K / 32;

    const int stm = t >> 1;
    const int stc = (t & 1) * 2;
    const int ssw = (stm & 7) >> 1;
    const __half* arow = Ah + (size_t)(bm + stm) * K + stc * 8;
    const __half* brow = BT + (size_t)(bn + stm) * K + stc * 8;
    const uint32_t adst0 = smb + (stm * 4 + (stc ^ ssw)) * 16;
    const uint32_t adst1 = smb + (stm * 4 + ((stc + 1) ^ ssw)) * 16;
    const uint32_t bdst0 = adst0 + 1024 * 16;
    const uint32_t bdst1 = adst1 + 1024 * 16;

    const int fr  = lane & 7;
    const int fg1 = (lane >> 3) & 1;
    const int fg2 = lane >> 4;
    const int rowA0 = wm + fr + fg1 * 8;
    const int swA   = (rowA0 & 7) >> 1;
    const int rowB0 = wn + fr + fg2 * 8;
    const int swB   = (rowB0 & 7) >> 1;
    const int cAa   = fg2;
    const int cBb   = fg1;

    float c[2][8][4];
#pragma unroll
    for (int u = 0; u < 2; u++)
#pragma unroll
        for (int j = 0; j < 8; j++)
#pragma unroll
            for (int q = 0; q < 4; q++) c[u][j][q] = 0.0f;

    CP16(adst0, arow); CP16(adst1, arow + 8);
    CP16(bdst0, brow); CP16(bdst1, brow + 8);
    CP_COMMIT();

    for (int kt = 0; kt < NK; kt++) {
        if (kt + 1 < NK) {
            const int s = (kt + 1) & 1;
            const int ko = (kt + 1) * 32;
            CP16(adst0 + s * 512 * 16, arow + ko);
            CP16(adst1 + s * 512 * 16, arow + ko + 8);
            CP16(bdst0 + s * 512 * 16, brow + ko);
            CP16(bdst1 + s * 512 * 16, brow + ko + 8);
            CP_COMMIT();
            CP_WAIT(1);
        } else {
            CP_WAIT(0);
        }
        __syncthreads();

        const uint32_t abase = smb + ((kt & 1) * 512) * 16;
        const uint32_t bbase = abase + 1024 * 16;

#pragma unroll
        for (int kc = 0; kc < 2; kc++) {
            uint32_t a[2][4];
#pragma unroll
            for (int u = 0; u < 2; u++) {
                const uint32_t ad = abase +
                    ((rowA0 + u * 16) * 4 + ((2 * kc + cAa) ^ swA)) * 16;
                LDSM4(a[u], ad);
            }
#pragma unroll
            for (int jp = 0; jp < 4; jp++) {
                uint32_t bb[4];
                const uint32_t bd = bbase +
                    ((rowB0 + jp * 16) * 4 + ((2 * kc + cBb) ^ swB)) * 16;
                LDSM4(bb, bd);
                MMA_F16(c[0][2 * jp],     a[0], bb[0], bb[1]);
                MMA_F16(c[1][2 * jp],     a[1], bb[0], bb[1]);
                MMA_F16(c[0][2 * jp + 1], a[0], bb[2], bb[3]);
                MMA_F16(c[1][2 * jp + 1], a[1], bb[2], bb[3]);
            }
        }
        __syncthreads();
    }

#pragma unroll
    for (int u = 0; u < 2; u++) {
        const int row = bm + wm + u * 16 + lr;
#pragma unroll
        for (int j = 0; j < 8; j++) {
            const int col = bn + wn + j * 8 + 2 * lc;
            const float bx = __ldg(&bias[col]);
            const float by = __ldg(&bias[col + 1]);
            const float v00 = c[u][j][0] + bx, v01 = c[u][j][1] + by;
            const float v10 = c[u][j][2] + bx, v11 = c[u][j][3] + by;
            if (Ch) {
                *(uint32_t*)((uint16_t*)Ch + (size_t)row * N + col) =
                    h2pack(v00, v01);
                *(uint32_t*)((uint16_t*)Ch + (size_t)(row + 8) * N + col) =
                    h2pack(v10, v11);
            } else {
                float2 w0 = { v00, v01 }, w1 = { v10, v11 };
                *(float2*)(Cf + (size_t)row * N + col)       = w0;
                *(float2*)(Cf + (size_t)(row + 8) * N + col) = w1;
            }
        }
    }
}

// ===========================================================================
// Flash attention fp16, register softmax, double-buffered K/V, 1 sync/tile.
// SMEM (uint4): Qs [0,1024), Ks stage s at 1024+s*512; Vt (uint) at 8192+s*2048.
// Total 48 KB.
// ===========================================================================
#define ATT_SMEM 49152

__global__ __launch_bounds__(256, 2) void attn16_kernel(
    const __half* __restrict__ qkvh, __half* __restrict__ outh)
{
    extern __shared__ uint4 smq[];
    const uint32_t smb = smem_u32(smq);
    uint32_t* VtU = (uint32_t*)smq + 8192;

    const int t    = threadIdx.x;
    const int lane = t & 31;
    const int lr   = lane >> 2;
    const int lc   = lane & 3;
    const int w    = t >> 5;
    const int wrow = w * 16;
    const int bh   = blockIdx.x;
    const int b    = bh >> 4, h = bh & 15;
    const int n0   = blockIdx.y * 128;

    const uint16_t* qkv16 = (const uint16_t*)qkvh;
    const uint16_t* qb = qkv16 + (size_t)(b * NSEQ + n0) * C3 + h * ND;
    const uint16_t* kb = qkv16 + (size_t)(b * NSEQ) * C3 + NC + h * ND;
    const uint16_t* vb = kb + NC;

    const int fr  = lane & 7;
    const int fg1 = (lane >> 3) & 1;
    const int fg2 = lane >> 4;

    // staging maps
    const int qm = t >> 1, qc0 = (t & 1) * 4;            // Q: 4 chunks
    const int kr = t >> 2, kc0 = 2 * (t & 3);            // K: 2 chunks
    const int kp = t >> 3, d0 = (t & 7) * 8;             // V: 2 rows x 8 halves
    const int vsw = (kp & 3) << 3;

    // ---- prologue: stage Q + K tile0 (cp.async), V tile0 (LDG/perm/STS) ----
    {
        const uint16_t* src = qb + (size_t)qm * C3 + qc0 * 8;
#pragma unroll
        for (int i = 0; i < 4; i++)
            CP16(smb + (qm * 8 + ((qc0 + i) ^ (qm & 7))) * 16, src + i * 8);
        const uint16_t* ks = kb + (size_t)kr * C3 + kc0 * 8;
#pragma unroll
        for (int i = 0; i < 2; i++)
            CP16(smb + (1024 + kr * 8 + ((kc0 + i) ^ (kr & 7))) * 16, ks + i * 8);
        CP_COMMIT();

        const uint4 u0 = *(const uint4*)(vb + (size_t)(2 * kp) * C3 + d0);
        const uint4 u1 = *(const uint4*)(vb + (size_t)(2 * kp + 1) * C3 + d0);
        uint4 x0 = { __byte_perm(u0.x, u1.x, 0x5410), __byte_perm(u0.x, u1.x, 0x7632),
                     __byte_perm(u0.y, u1.y, 0x5410), __byte_perm(u0.y, u1.y, 0x7632) };
        uint4 x1 = { __byte_perm(u0.z, u1.z, 0x5410), __byte_perm(u0.z, u1.z, 0x7632),
                     __byte_perm(u0.w, u1.w, 0x5410), __byte_perm(u0.w, u1.w, 0x7632) };
        *(uint4*)(VtU + kp * 64 + (d0 ^ vsw))     = x0;
        *(uint4*)(VtU + kp * 64 + (d0 ^ vsw) + 4) = x1;
    }
    CP_WAIT(0);
    __syncthreads();

    // ---- Q frags ----
    uint32_t qf[4][4];
#pragma unroll
    for (int kc = 0; kc < 4; kc++) {
        const int rowQ = wrow + fr + fg1 * 8;
        const int cQ = 2 * kc + fg2;
        LDSM4(qf[kc], smb + (rowQ * 8 + (cQ ^ (rowQ & 7))) * 16);
    }

    float o[8][4];
#pragma unroll
    for (int j = 0; j < 8; j++)
#pragma unroll
        for (int q = 0; q < 4; q++) o[j][q] = 0.0f;
    float m0 = -1e30f, m1 = -1e30f, l0 = 0.0f, l1 = 0.0f;

    for (int ti = 0; ti < NSEQ / 64; ti++) {
        const int s = ti & 1;
        const uint32_t ksb = smb + (1024 + s * 512) * 16;
        uint32_t* vcur = VtU + s * 2048;

        // prefetch next tile: K via cp.async, V into regs
        uint4 pv0, pv1;
        const int more = (ti + 1 < NSEQ / 64);
        if (more) {
            const uint16_t* ks = kb + (size_t)((ti + 1) * 64 + kr) * C3 + kc0 * 8;
#pragma unroll
            for (int i = 0; i < 2; i++)
                CP16(smb + (1024 + (s ^ 1) * 512 + kr * 8 + ((kc0 + i) ^ (kr & 7))) * 16,
                     ks + i * 8);
            CP_COMMIT();
            pv0 = *(const uint4*)(vb + (size_t)((ti + 1) * 64 + 2 * kp) * C3 + d0);
            pv1 = *(const uint4*)(vb + (size_t)((ti + 1) * 64 + 2 * kp + 1) * C3 + d0);
        }

        // ---- S = Q @ K^T ----
        float sacc[8][4];
#pragma unroll
        for (int j = 0; j < 8; j++)
#pragma unroll
            for (int q = 0; q < 4; q++) sacc[j][q] = 0.0f;

#pragma unroll
        for (int kc = 0; kc < 4; kc++) {
#pragma unroll
            for (int jp = 0; jp < 4; jp++) {
                uint32_t bb[4];
                const int rowK = jp * 16 + fr + fg2 * 8;
                const int cK = 2 * kc + fg1;
                LDSM4(bb, ksb + (rowK * 8 + ((cK ^ (rowK & 7)))) * 16);
                MMA_F16(sacc[2 * jp],     qf[kc], bb[0], bb[1]);
                MMA_F16(sacc[2 * jp + 1], qf[kc], bb[2], bb[3]);
            }
        }

        // ---- register softmax (scale 1/8 folded) ----
        float rm0 = sacc[0][0], rm1 = sacc[0][2];
#pragma unroll
        for (int j = 0; j < 8; j++) {
            rm0 = fmaxf(rm0, fmaxf(sacc[j][0], sacc[j][1]));
            rm1 = fmaxf(rm1, fmaxf(sacc[j][2], sacc[j][3]));
        }
        rm0 = fmaxf(rm0, __shfl_xor_sync(0xffffffffu, rm0, 1));
        rm0 = fmaxf(rm0, __shfl_xor_sync(0xffffffffu, rm0, 2));
        rm1 = fmaxf(rm1, __shfl_xor_sync(0xffffffffu, rm1, 1));
        rm1 = fmaxf(rm1, __shfl_xor_sync(0xffffffffu, rm1, 2));
        const float m0n = fmaxf(m0, 0.125f * rm0);
        const float m1n = fmaxf(m1, 0.125f * rm1);
        const float al0 = __expf(m0 - m0n);
        const float al1 = __expf(m1 - m1n);
        m0 = m0n; m1 = m1n;
#pragma unroll
        for (int j = 0; j < 8; j++) {
            o[j][0] *= al0; o[j][1] *= al0;
            o[j][2] *= al1; o[j][3] *= al1;
        }
        l0 *= al0; l1 *= al1;

        // ---- per-chunk: exp + pack P frags + PV MMA ----
        const int kkb = lc;
        const int psw = lc << 3;
        float ls0 = 0.0f, ls1 = 0.0f;
#pragma unroll
        for (int kc = 0; kc < 4; kc++) {
            uint32_t pa[4];
#pragma unroll
            for (int jj = 0; jj < 2; jj++) {
                const int j = 2 * kc + jj;
                const float p0 = __expf(fmaf(sacc[j][0], 0.125f, -m0n));
                const float p1 = __expf(fmaf(sacc[j][1], 0.125f, -m0n));
                const float p2 = __expf(fmaf(sacc[j][2], 0.125f, -m1n));
                const float p3 = __expf(fmaf(sacc[j][3], 0.125f, -m1n));
                ls0 += p0 + p1; ls1 += p2 + p3;
                pa[2 * jj]     = h2pack(p0, p1);
                pa[2 * jj + 1] = h2pack(p2, p3);
            }
            const int kk = 8 * kc + kkb;
#pragma unroll
            for (int j = 0; j < 8; j++) {
                const int col = (8 * j + lr) ^ psw;
                const uint32_t b0 = vcur[kk * 64 + col];
                const uint32_t b1 = vcur[(kk + 4) * 64 + col];
                MMA_F16(o[j], pa, b0, b1);
            }
        }
        ls0 += __shfl_xor_sync(0xffffffffu, ls0, 1);
        ls0 += __shfl_xor_sync(0xffffffffu, ls0, 2);
        ls1 += __shfl_xor_sync(0xffffffffu, ls1, 1);
        ls1 += __shfl_xor_sync(0xffffffffu, ls1, 2);
        l0 += ls0; l1 += ls1;

        // ---- store prefetched V into other stage ----
        if (more) {
            uint32_t* vnxt = VtU + (s ^ 1) * 2048;
            uint4 x0 = { __byte_perm(pv0.x, pv1.x, 0x5410), __byte_perm(pv0.x, pv1.x, 0x7632),
                         __byte_perm(pv0.y, pv1.y, 0x5410), __byte_perm(pv0.y, pv1.y, 0x7632) };
            uint4 x1 = { __byte_perm(pv0.z, pv1.z, 0x5410), __byte_perm(pv0.z, pv1.z, 0x7632),
                         __byte_perm(pv0.w, pv1.w, 0x5410), __byte_perm(pv0.w, pv1.w, 0x7632) };
            *(uint4*)(vnxt + kp * 64 + (d0 ^ vsw))     = x0;
            *(uint4*)(vnxt + kp * 64 + (d0 ^ vsw) + 4) = x1;
        }
        CP_WAIT(0);
        __syncthreads();
    }

    // ---- epilogue: O /= l, fp16 out [B,N,H*D] ----
    {
        const float li0 = 1.0f / l0;
        const float li1 = 1.0f / l1;
        uint16_t* ob = (uint16_t*)outh;
        const size_t r0 = (size_t)(b * NSEQ + n0 + wrow + lr) * NC + h * ND;
        const size_t r1 = r0 + (size_t)8 * NC;
#pragma unroll
        for (int j = 0; j < 8; j++) {
            const int col = 8 * j + 2 * lc;
            *(uint32_t*)(ob + r0 + col) = h2pack(o[j][0] * li0, o[j][1] * li0);
            *(uint32_t*)(ob + r1 + col) = h2pack(o[j][2] * li1, o[j][3] * li1);
        }
    }
}

// ---------------------------------------------------------------------------
extern "C" void kernel_launch(void* const* d_in, const int* in_sizes, int n_in,
                              void* d_out, int out_size)
{
    const float* x     = (const float*)d_in[0];
    const float* w_qkv = (const float*)d_in[1];
    const float* b_qkv = (const float*)d_in[2];
    const float* w_out = (const float*)d_in[3];
    const float* b_out = (const float*)d_in[4];
    float* out = (float*)d_out;

    __half *xh, *qkvh, *attnh, *wqkvT, *woutT;
    cudaGetSymbolAddress((void**)&xh, g_xh);
    cudaGetSymbolAddress((void**)&qkvh, g_qkvh);
    cudaGetSymbolAddress((void**)&attnh, g_attnh);
    cudaGetSymbolAddress((void**)&wqkvT, g_wqkvT);
    cudaGetSymbolAddress((void**)&woutT, g_woutT);

    cudaFuncSetAttribute(gemm16_kernel,
                         cudaFuncAttributeMaxDynamicSharedMemorySize, GEMM_SMEM);
    cudaFuncSetAttribute(attn16_kernel,
                         cudaFuncAttributeMaxDynamicSharedMemorySize, ATT_SMEM);

    // 0) prep
    cvt_x_kernel<<<NTOK * NC / 1024, 256>>>(x, xh);
    {
        dim3 blk(32, 8);
        dim3 g1(C3 / 32, NC / 32);
        wT_kernel<<<g1, blk>>>(w_qkv, wqkvT, NC, C3);
        dim3 g2(NC / 32, NC / 32);
        wT_kernel<<<g2, blk>>>(w_out, woutT, NC, NC);
    }
    // 1) qkv = x @ w_qkv + b_qkv   (fp16 out)
    {
        dim3 grid(C3 / 128, NTOK / 128);
        gemm16_kernel<<<grid, 256, GEMM_SMEM>>>(xh, wqkvT, b_qkv,
                                                nullptr, qkvh, NTOK, C3, NC);
    }
    // 2) flash attention
    {
        dim3 grid(NB * NH, NSEQ / 128);
        attn16_kernel<<<grid, 256, ATT_SMEM>>>(qkvh, attnh);
    }
    // 3) out = attn @ w_out + b_out (fp32 out)
    {
        dim3 grid(NC / 128, NTOK / 128);
        gemm16_kernel<<<grid, 256, GEMM_SMEM>>>(attnh, woutT, b_out,
                                                out, nullptr, NTOK, NC, NC);
    }
}

// round 16
// speedup vs baseline: 11.9779x; 1.1002x over previous
#include <cuda_runtime.h>
#include <cuda_fp16.h>
#include <cstdint>

// ---------------------------------------------------------------------------
// MultiHeadSelfAttention: B=2, N=2048, C=1024, H=16, D=64, fp32 in/out.
//   prep:  x->fp16, w_qkv->fp16 [N][K], w_out->fp16 [N][K]
//   gemm1: qkv_h = xh @ wqkvT^T + b      (fp16 out)   4-stage cp.async pipe
//   attn:  flash attention, fp16 HMMA, register softmax (base-2 exp)
//   gemm3: out = attnh @ woutT^T + b     (fp32 out)
// ---------------------------------------------------------------------------

#define NB    2
#define NSEQ  2048
#define NC    1024
#define NH    16
#define ND    64
#define NTOK  (NB * NSEQ)       // 4096
#define C3    (3 * NC)          // 3072

__device__ __half g_xh[NTOK * NC];
__device__ __half g_qkvh[NTOK * C3];
__device__ __half g_attnh[NTOK * NC];
__device__ __half g_wqkvT[C3 * NC];
__device__ __half g_woutT[NC * NC];

// ---------------- helpers ----------------
__device__ __forceinline__ uint32_t smem_u32(const void* p) {
    uint32_t a;
    asm("{ .reg .u64 t; cvta.to.shared.u64 t, %1; cvt.u32.u64 %0, t; }"
        : "=r"(a) : "l"(p));
    return a;
}
__device__ __forceinline__ uint32_t h2pack(float lo, float hi) {
    uint32_t r;
    asm("cvt.rn.f16x2.f32 %0, %1, %2;" : "=r"(r) : "f"(hi), "f"(lo));
    return r;
}
__device__ __forceinline__ float ex2(float x) {
    float r;
    asm("ex2.approx.ftz.f32 %0, %1;" : "=f"(r) : "f"(x));
    return r;
}

#define MMA_F16(cc, aa, b0v, b1v)                                             \
    asm volatile("mma.sync.aligned.m16n8k16.row.col.f32.f16.f16.f32 "         \
                 "{%0,%1,%2,%3}, {%4,%5,%6,%7}, {%8,%9}, {%0,%1,%2,%3};"      \
                 : "+f"((cc)[0]), "+f"((cc)[1]), "+f"((cc)[2]), "+f"((cc)[3]) \
                 : "r"((aa)[0]), "r"((aa)[1]), "r"((aa)[2]), "r"((aa)[3]),    \
                   "r"(b0v), "r"(b1v))

#define LDSM4(R, addr)                                                        \
    asm volatile("ldmatrix.sync.aligned.m8n8.x4.shared.b16 {%0,%1,%2,%3}, [%4];" \
                 : "=r"((R)[0]), "=r"((R)[1]), "=r"((R)[2]), "=r"((R)[3])     \
                 : "r"(addr))

#define CP16(dst, src)                                                        \
    asm volatile("cp.async.cg.shared.global [%0], [%1], 16;"                  \
                 :: "r"(dst), "l"(src) : "memory")
#define CP_COMMIT() asm volatile("cp.async.commit_group;" ::: "memory")
#define CP_WAIT(n)  asm volatile("cp.async.wait_group %0;" :: "n"(n) : "memory")

// ===========================================================================
// Prep kernels
// ===========================================================================
__global__ __launch_bounds__(256) void cvt_x_kernel(
    const float* __restrict__ in, __half* __restrict__ out)
{
    const int i = (blockIdx.x * 256 + threadIdx.x) * 4;
    float4 v = *(const float4*)(in + i);
    uint2 w = { h2pack(v.x, v.y), h2pack(v.z, v.w) };
    *(uint2*)((uint16_t*)out + i) = w;
}

__global__ void wT_kernel(const float* __restrict__ in,
                          __half* __restrict__ out, int R, int Cc)
{
    __shared__ float tile[32][33];
    const int c0 = blockIdx.x * 32, r0 = blockIdx.y * 32;
#pragma unroll
    for (int i = threadIdx.y; i < 32; i += 8)
        tile[i][threadIdx.x] = in[(size_t)(r0 + i) * Cc + c0 + threadIdx.x];
    __syncthreads();
#pragma unroll
    for (int i = threadIdx.y; i < 32; i += 8)
        out[(size_t)(c0 + i) * R + r0 + threadIdx.x] =
            __float2half_rn(tile[threadIdx.x][i]);
}

// ===========================================================================
// GEMM fp16:  C[M,N] = A[M,K] @ BT[N,K]^T + bias.  4-stage cp.async pipeline.
// SMEM uint4: A stage s at s*512, B stage s at 2048+s*512  (64 KB total).
// ===========================================================================
#define GEMM_SMEM (4096 * 16)

__global__ __launch_bounds__(256, 2) void gemm16_kernel(
    const __half* __restrict__ Ah, const __half* __restrict__ BT,
    const float* __restrict__ bias, float* __restrict__ Cf,
    __half* __restrict__ Ch, int M, int N, int K)
{
    extern __shared__ uint4 smq[];
    const uint32_t smb = smem_u32(smq);

    const int t    = threadIdx.x;
    const int lane = t & 31;
    const int lr   = lane >> 2;
    const int lc   = lane & 3;
    const int wm   = ((t >> 5) & 3) * 32;
    const int wn   = (t >> 7) * 64;
    const int bm   = blockIdx.y * 128;
    const int bn   = blockIdx.x * 128;
    const int NK   = K / 32;

    // staging map
    const int stm = t >> 1;
    const int stc = (t & 1) * 2;
    const int ssw = (stm & 7) >> 1;
    const __half* arow = Ah + (size_t)(bm + stm) * K + stc * 8;
    const __half* brow = BT + (size_t)(bn + stm) * K + stc * 8;
    const uint32_t adst0 = smb + (stm * 4 + (stc ^ ssw)) * 16;
    const uint32_t adst1 = smb + (stm * 4 + ((stc + 1) ^ ssw)) * 16;
    const uint32_t bdst0 = adst0 + 2048 * 16;
    const uint32_t bdst1 = adst1 + 2048 * 16;

    // fragment address components
    const int fr  = lane & 7;
    const int fg1 = (lane >> 3) & 1;
    const int fg2 = lane >> 4;
    const int rowA0 = wm + fr + fg1 * 8;
    const int swA   = (rowA0 & 7) >> 1;
    const int rowB0 = wn + fr + fg2 * 8;
    const int swB   = (rowB0 & 7) >> 1;
    const int cAa   = fg2;
    const int cBb   = fg1;

    float c[2][8][4];
#pragma unroll
    for (int u = 0; u < 2; u++)
#pragma unroll
        for (int j = 0; j < 8; j++)
#pragma unroll
            for (int q = 0; q < 4; q++) c[u][j][q] = 0.0f;

    // ---- prologue: issue stages 0,1,2 ----
#pragma unroll
    for (int s = 0; s < 3; s++) {
        const int ko = s * 32;
        const uint32_t so = s * 512 * 16;
        CP16(adst0 + so, arow + ko); CP16(adst1 + so, arow + ko + 8);
        CP16(bdst0 + so, brow + ko); CP16(bdst1 + so, brow + ko + 8);
        CP_COMMIT();
    }

    for (int kt = 0; kt < NK; kt++) {
        CP_WAIT(2);          // stage kt complete; kt+1,kt+2 in flight
        __syncthreads();     // all threads see stage kt; prior reads of
                             // stage (kt+3)&3 (read at kt-1) are done
        if (kt + 3 < NK) {
            const int s = (kt + 3) & 3;
            const int ko = (kt + 3) * 32;
            const uint32_t so = s * 512 * 16;
            CP16(adst0 + so, arow + ko); CP16(adst1 + so, arow + ko + 8);
            CP16(bdst0 + so, brow + ko); CP16(bdst1 + so, brow + ko + 8);
        }
        CP_COMMIT();         // always commit (empty groups keep count aligned)

        const uint32_t abase = smb + ((kt & 3) * 512) * 16;
        const uint32_t bbase = abase + 2048 * 16;

#pragma unroll
        for (int kc = 0; kc < 2; kc++) {
            uint32_t a[2][4];
#pragma unroll
            for (int u = 0; u < 2; u++) {
                const uint32_t ad = abase +
                    ((rowA0 + u * 16) * 4 + ((2 * kc + cAa) ^ swA)) * 16;
                LDSM4(a[u], ad);
            }
#pragma unroll
            for (int jp = 0; jp < 4; jp++) {
                uint32_t bb[4];
                const uint32_t bd = bbase +
                    ((rowB0 + jp * 16) * 4 + ((2 * kc + cBb) ^ swB)) * 16;
                LDSM4(bb, bd);
                MMA_F16(c[0][2 * jp],     a[0], bb[0], bb[1]);
                MMA_F16(c[1][2 * jp],     a[1], bb[0], bb[1]);
                MMA_F16(c[0][2 * jp + 1], a[0], bb[2], bb[3]);
                MMA_F16(c[1][2 * jp + 1], a[1], bb[2], bb[3]);
            }
        }
    }

    // ---- epilogue ----
#pragma unroll
    for (int u = 0; u < 2; u++) {
        const int row = bm + wm + u * 16 + lr;
#pragma unroll
        for (int j = 0; j < 8; j++) {
            const int col = bn + wn + j * 8 + 2 * lc;
            const float bx = __ldg(&bias[col]);
            const float by = __ldg(&bias[col + 1]);
            const float v00 = c[u][j][0] + bx, v01 = c[u][j][1] + by;
            const float v10 = c[u][j][2] + bx, v11 = c[u][j][3] + by;
            if (Ch) {
                *(uint32_t*)((uint16_t*)Ch + (size_t)row * N + col) =
                    h2pack(v00, v01);
                *(uint32_t*)((uint16_t*)Ch + (size_t)(row + 8) * N + col) =
                    h2pack(v10, v11);
            } else {
                float2 w0 = { v00, v01 }, w1 = { v10, v11 };
                *(float2*)(Cf + (size_t)row * N + col)       = w0;
                *(float2*)(Cf + (size_t)(row + 8) * N + col) = w1;
            }
        }
    }
}

// ===========================================================================
// Flash attention fp16, register softmax (base-2 exp), double-buffered K/V.
// SMEM (uint4): Qs [0,1024), Ks stage s at 1024+s*512; Vt (uint) at 8192+s*2048.
// ===========================================================================
#define ATT_SMEM 49152
#define L2E8 0.180336880111120f   // 0.125 * log2(e)

__global__ __launch_bounds__(256, 2) void attn16_kernel(
    const __half* __restrict__ qkvh, __half* __restrict__ outh)
{
    extern __shared__ uint4 smq[];
    const uint32_t smb = smem_u32(smq);
    uint32_t* VtU = (uint32_t*)smq + 8192;

    const int t    = threadIdx.x;
    const int lane = t & 31;
    const int lr   = lane >> 2;
    const int lc   = lane & 3;
    const int w    = t >> 5;
    const int wrow = w * 16;
    const int bh   = blockIdx.x;
    const int b    = bh >> 4, h = bh & 15;
    const int n0   = blockIdx.y * 128;

    const uint16_t* qkv16 = (const uint16_t*)qkvh;
    const uint16_t* qb = qkv16 + (size_t)(b * NSEQ + n0) * C3 + h * ND;
    const uint16_t* kb = qkv16 + (size_t)(b * NSEQ) * C3 + NC + h * ND;
    const uint16_t* vb = kb + NC;

    const int fr  = lane & 7;
    const int fg1 = (lane >> 3) & 1;
    const int fg2 = lane >> 4;

    const int qm = t >> 1, qc0 = (t & 1) * 4;
    const int kr = t >> 2, kc0 = 2 * (t & 3);
    const int kp = t >> 3, d0 = (t & 7) * 8;
    const int vsw = (kp & 3) << 3;

    // ---- prologue ----
    {
        const uint16_t* src = qb + (size_t)qm * C3 + qc0 * 8;
#pragma unroll
        for (int i = 0; i < 4; i++)
            CP16(smb + (qm * 8 + ((qc0 + i) ^ (qm & 7))) * 16, src + i * 8);
        const uint16_t* ks = kb + (size_t)kr * C3 + kc0 * 8;
#pragma unroll
        for (int i = 0; i < 2; i++)
            CP16(smb + (1024 + kr * 8 + ((kc0 + i) ^ (kr & 7))) * 16, ks + i * 8);
        CP_COMMIT();

        const uint4 u0 = *(const uint4*)(vb + (size_t)(2 * kp) * C3 + d0);
        const uint4 u1 = *(const uint4*)(vb + (size_t)(2 * kp + 1) * C3 + d0);
        uint4 x0 = { __byte_perm(u0.x, u1.x, 0x5410), __byte_perm(u0.x, u1.x, 0x7632),
                     __byte_perm(u0.y, u1.y, 0x5410), __byte_perm(u0.y, u1.y, 0x7632) };
        uint4 x1 = { __byte_perm(u0.z, u1.z, 0x5410), __byte_perm(u0.z, u1.z, 0x7632),
                     __byte_perm(u0.w, u1.w, 0x5410), __byte_perm(u0.w, u1.w, 0x7632) };
        *(uint4*)(VtU + kp * 64 + (d0 ^ vsw))     = x0;
        *(uint4*)(VtU + kp * 64 + (d0 ^ vsw) + 4) = x1;
    }
    CP_WAIT(0);
    __syncthreads();

    uint32_t qf[4][4];
#pragma unroll
    for (int kc = 0; kc < 4; kc++) {
        const int rowQ = wrow + fr + fg1 * 8;
        const int cQ = 2 * kc + fg2;
        LDSM4(qf[kc], smb + (rowQ * 8 + (cQ ^ (rowQ & 7))) * 16);
    }

    float o[8][4];
#pragma unroll
    for (int j = 0; j < 8; j++)
#pragma unroll
        for (int q = 0; q < 4; q++) o[j][q] = 0.0f;
    float m0 = -1e30f, m1 = -1e30f, l0 = 0.0f, l1 = 0.0f;   // m in log2 domain

    for (int ti = 0; ti < NSEQ / 64; ti++) {
        const int s = ti & 1;
        const uint32_t ksb = smb + (1024 + s * 512) * 16;
        uint32_t* vcur = VtU + s * 2048;

        uint4 pv0, pv1;
        const int more = (ti + 1 < NSEQ / 64);
        if (more) {
            const uint16_t* ks = kb + (size_t)((ti + 1) * 64 + kr) * C3 + kc0 * 8;
#pragma unroll
            for (int i = 0; i < 2; i++)
                CP16(smb + (1024 + (s ^ 1) * 512 + kr * 8 + ((kc0 + i) ^ (kr & 7))) * 16,
                     ks + i * 8);
            CP_COMMIT();
            pv0 = *(const uint4*)(vb + (size_t)((ti + 1) * 64 + 2 * kp) * C3 + d0);
            pv1 = *(const uint4*)(vb + (size_t)((ti + 1) * 64 + 2 * kp + 1) * C3 + d0);
        }

        // ---- S = Q @ K^T ----
        float sacc[8][4];
#pragma unroll
        for (int j = 0; j < 8; j++)
#pragma unroll
            for (int q = 0; q < 4; q++) sacc[j][q] = 0.0f;

#pragma unroll
        for (int kc = 0; kc < 4; kc++) {
#pragma unroll
            for (int jp = 0; jp < 4; jp++) {
                uint32_t bb[4];
                const int rowK = jp * 16 + fr + fg2 * 8;
                const int cK = 2 * kc + fg1;
                LDSM4(bb, ksb + (rowK * 8 + ((cK ^ (rowK & 7)))) * 16);
                MMA_F16(sacc[2 * jp],     qf[kc], bb[0], bb[1]);
                MMA_F16(sacc[2 * jp + 1], qf[kc], bb[2], bb[3]);
            }
        }

        // ---- register softmax (base-2 domain) ----
        float rm0 = sacc[0][0], rm1 = sacc[0][2];
#pragma unroll
        for (int j = 0; j < 8; j++) {
            rm0 = fmaxf(rm0, fmaxf(sacc[j][0], sacc[j][1]));
            rm1 = fmaxf(rm1, fmaxf(sacc[j][2], sacc[j][3]));
        }
        rm0 = fmaxf(rm0, __shfl_xor_sync(0xffffffffu, rm0, 1));
        rm0 = fmaxf(rm0, __shfl_xor_sync(0xffffffffu, rm0, 2));
        rm1 = fmaxf(rm1, __shfl_xor_sync(0xffffffffu, rm1, 1));
        rm1 = fmaxf(rm1, __shfl_xor_sync(0xffffffffu, rm1, 2));
        const float m0n = fmaxf(m0, L2E8 * rm0);
        const float m1n = fmaxf(m1, L2E8 * rm1);
        const float al0 = ex2(m0 - m0n);
        const float al1 = ex2(m1 - m1n);
        m0 = m0n; m1 = m1n;
#pragma unroll
        for (int j = 0; j < 8; j++) {
            o[j][0] *= al0; o[j][1] *= al0;
            o[j][2] *= al1; o[j][3] *= al1;
        }
        l0 *= al0; l1 *= al1;

        // ---- exp + pack P frags + PV MMA ----
        const int psw = lc << 3;
        float ls0 = 0.0f, ls1 = 0.0f;
#pragma unroll
        for (int kc = 0; kc < 4; kc++) {
            uint32_t pa[4];
#pragma unroll
            for (int jj = 0; jj < 2; jj++) {
                const int j = 2 * kc + jj;
                const float p0 = ex2(fmaf(sacc[j][0], L2E8, -m0n));
                const float p1 = ex2(fmaf(sacc[j][1], L2E8, -m0n));
                const float p2 = ex2(fmaf(sacc[j][2], L2E8, -m1n));
                const float p3 = ex2(fmaf(sacc[j][3], L2E8, -m1n));
                ls0 += p0 + p1; ls1 += p2 + p3;
                pa[2 * jj]     = h2pack(p0, p1);
                pa[2 * jj + 1] = h2pack(p2, p3);
            }
            const int kk = 8 * kc + lc;
#pragma unroll
            for (int j = 0; j < 8; j++) {
                const int col = (8 * j + lr) ^ psw;
                const uint32_t b0 = vcur[kk * 64 + col];
                const uint32_t b1 = vcur[(kk + 4) * 64 + col];
                MMA_F16(o[j], pa, b0, b1);
            }
        }
        ls0 += __shfl_xor_sync(0xffffffffu, ls0, 1);
        ls0 += __shfl_xor_sync(0xffffffffu, ls0, 2);
        ls1 += __shfl_xor_sync(0xffffffffu, ls1, 1);
        ls1 += __shfl_xor_sync(0xffffffffu, ls1, 2);
        l0 += ls0; l1 += ls1;

        if (more) {
            uint32_t* vnxt = VtU + (s ^ 1) * 2048;
            uint4 x0 = { __byte_perm(pv0.x, pv1.x, 0x5410), __byte_perm(pv0.x, pv1.x, 0x7632),
                         __byte_perm(pv0.y, pv1.y, 0x5410), __byte_perm(pv0.y, pv1.y, 0x7632) };
            uint4 x1 = { __byte_perm(pv0.z, pv1.z, 0x5410), __byte_perm(pv0.z, pv1.z, 0x7632),
                         __byte_perm(pv0.w, pv1.w, 0x5410), __byte_perm(pv0.w, pv1.w, 0x7632) };
            *(uint4*)(vnxt + kp * 64 + (d0 ^ vsw))     = x0;
            *(uint4*)(vnxt + kp * 64 + (d0 ^ vsw) + 4) = x1;
        }
        CP_WAIT(0);
        __syncthreads();
    }

    // ---- epilogue ----
    {
        const float li0 = 1.0f / l0;
        const float li1 = 1.0f / l1;
        uint16_t* ob = (uint16_t*)outh;
        const size_t r0 = (size_t)(b * NSEQ + n0 + wrow + lr) * NC + h * ND;
        const size_t r1 = r0 + (size_t)8 * NC;
#pragma unroll
        for (int j = 0; j < 8; j++) {
            const int col = 8 * j + 2 * lc;
            *(uint32_t*)(ob + r0 + col) = h2pack(o[j][0] * li0, o[j][1] * li0);
            *(uint32_t*)(ob + r1 + col) = h2pack(o[j][2] * li1, o[j][3] * li1);
        }
    }
}

// ---------------------------------------------------------------------------
extern "C" void kernel_launch(void* const* d_in, const int* in_sizes, int n_in,
                              void* d_out, int out_size)
{
    const float* x     = (const float*)d_in[0];
    const float* w_qkv = (const float*)d_in[1];
    const float* b_qkv = (const float*)d_in[2];
    const float* w_out = (const float*)d_in[3];
    const float* b_out = (const float*)d_in[4];
    float* out = (float*)d_out;

    __half *xh, *qkvh, *attnh, *wqkvT, *woutT;
    cudaGetSymbolAddress((void**)&xh, g_xh);
    cudaGetSymbolAddress((void**)&qkvh, g_qkvh);
    cudaGetSymbolAddress((void**)&attnh, g_attnh);
    cudaGetSymbolAddress((void**)&wqkvT, g_wqkvT);
    cudaGetSymbolAddress((void**)&woutT, g_woutT);

    cudaFuncSetAttribute(gemm16_kernel,
                         cudaFuncAttributeMaxDynamicSharedMemorySize, GEMM_SMEM);
    cudaFuncSetAttribute(attn16_kernel,
                         cudaFuncAttributeMaxDynamicSharedMemorySize, ATT_SMEM);

    // 0) prep
    cvt_x_kernel<<<NTOK * NC / 1024, 256>>>(x, xh);
    {
        dim3 blk(32, 8);
        dim3 g1(C3 / 32, NC / 32);
        wT_kernel<<<g1, blk>>>(w_qkv, wqkvT, NC, C3);
        dim3 g2(NC / 32, NC / 32);
        wT_kernel<<<g2, blk>>>(w_out, woutT, NC, NC);
    }
    // 1) qkv = x @ w_qkv + b_qkv   (fp16 out)
    {
        dim3 grid(C3 / 128, NTOK / 128);
        gemm16_kernel<<<grid, 256, GEMM_SMEM>>>(xh, wqkvT, b_qkv,
                                                nullptr, qkvh, NTOK, C3, NC);
    }
    // 2) flash attention
    {
        dim3 grid(NB * NH, NSEQ / 128);
        attn16_kernel<<<grid, 256, ATT_SMEM>>>(qkvh, attnh);
    }
    // 3) out = attn @ w_out + b_out (fp32 out)
    {
        dim3 grid(NC / 128, NTOK / 128);
        gemm16_kernel<<<grid, 256, GEMM_SMEM>>>(attnh, woutT, b_out,
                                                out, nullptr, NTOK, NC, NC);
    }
}